// round 2
// baseline (speedup 1.0000x reference)
#include <cuda_runtime.h>

// Problem constants
#define T_  4
#define B_  8
#define C_  512
#define D_  768
#define H_  12
#define DH  64
#define BC  (B_*C_)          // 4096
#define BCD (BC*D_)          // 3145728
#define NBH (B_*H_)          // 96

// Persistent scratch (allocation-free: __device__ globals)
__device__ float  g_mem[5][BCD];          // memq, memk, memv, mematt, mproj
__device__ float  g_spk[4][BCD];          // sq, sk, sv, satt
__device__ float  g_x2[BCD];              // projection output (pre-BN)
__device__ float  g_attn[NBH * C_ * C_];  // [96][512][512]
__device__ double g_psumd[8 * D_];
__device__ double g_pvard[8 * D_];
__device__ float  g_mean[D_];
__device__ float  g_rstd[D_];

// TF32 rounding (matches tensor-core input rounding used by cuBLAS TF32 GEMM)
__device__ __forceinline__ float tf32r(float x) {
    unsigned u;
    asm("cvt.rna.tf32.f32 %0, %1;" : "=r"(u) : "f"(x));
    return __uint_as_float(u);
}

// ---------------------------------------------------------------------------
__global__ void zero_mem_kernel() {
    size_t n = (size_t)5 * BCD;
    float* p = &g_mem[0][0];
    for (size_t i = (size_t)blockIdx.x * blockDim.x + threadIdx.x; i < n;
         i += (size_t)gridDim.x * blockDim.x)
        p[i] = 0.0f;
}

// ---------------------------------------------------------------------------
// vout = broadcast v to [T, T, B, C, D]  (4 copies of full v)
__global__ void vout_copy_kernel(const float* __restrict__ v, float* __restrict__ o) {
    const size_t n4 = (size_t)T_ * BCD / 4;  // float4 count of one copy
    size_t i = (size_t)blockIdx.x * blockDim.x + threadIdx.x;
    if (i < n4) {
        float4 val = ((const float4*)v)[i];
        float4* o4 = (float4*)o;
        o4[i]          = val;
        o4[i + n4]     = val;
        o4[i + 2 * n4] = val;
        o4[i + 3 * n4] = val;
    }
}

// ---------------------------------------------------------------------------
// Dense GEMM: out[m,n] = sum_k tf32(X[m,k]) * tf32(W[n,k]) + bias[n]
// M=4096, N=768, K=768. Tile 128x128, BK=16, 256 threads, 8x8 per thread.
__global__ __launch_bounds__(256) void dense_gemm_lif(
    const float* __restrict__ Xq, const float* __restrict__ Xk, const float* __restrict__ Xv,
    const float* __restrict__ Wq, const float* __restrict__ Wk, const float* __restrict__ Wv,
    const float* __restrict__ bq, const float* __restrict__ bk, const float* __restrict__ bv,
    int mode)
{
    __shared__ float As[16 * 128];
    __shared__ float Bs[16 * 128];

    const int z = blockIdx.z;
    const float* X;
    const float* W;
    const float* bias;
    float* mem = nullptr;
    float* spk = nullptr;
    float* out = nullptr;
    if (mode) {
        X    = (z == 0) ? Xq : ((z == 1) ? Xk : Xv);
        W    = (z == 0) ? Wq : ((z == 1) ? Wk : Wv);
        bias = (z == 0) ? bq : ((z == 1) ? bk : bv);
        mem  = g_mem[z];
        spk  = g_spk[z];
    } else {
        X = g_spk[3]; W = Wq; bias = bq; out = g_x2;
    }

    const int t  = threadIdx.x;
    const int m0 = blockIdx.y * 128;
    const int n0 = blockIdx.x * 128;
    const int ty = t >> 4, tx = t & 15;

    float acc[8][8];
#pragma unroll
    for (int i = 0; i < 8; i++)
#pragma unroll
        for (int j = 0; j < 8; j++) acc[i][j] = 0.0f;

    for (int k0 = 0; k0 < 768; k0 += 16) {
#pragma unroll
        for (int r = 0; r < 2; r++) {
            int id  = t + 256 * r;
            int row = id >> 2, seg = id & 3;
            float4 xa = *(const float4*)&X[(size_t)(m0 + row) * 768 + k0 + seg * 4];
            As[(seg * 4 + 0) * 128 + row] = tf32r(xa.x);
            As[(seg * 4 + 1) * 128 + row] = tf32r(xa.y);
            As[(seg * 4 + 2) * 128 + row] = tf32r(xa.z);
            As[(seg * 4 + 3) * 128 + row] = tf32r(xa.w);
            float4 wb = *(const float4*)&W[(size_t)(n0 + row) * 768 + k0 + seg * 4];
            Bs[(seg * 4 + 0) * 128 + row] = tf32r(wb.x);
            Bs[(seg * 4 + 1) * 128 + row] = tf32r(wb.y);
            Bs[(seg * 4 + 2) * 128 + row] = tf32r(wb.z);
            Bs[(seg * 4 + 3) * 128 + row] = tf32r(wb.w);
        }
        __syncthreads();
#pragma unroll
        for (int k = 0; k < 16; k++) {
            float a[8], b[8];
            *(float4*)&a[0] = *(float4*)&As[k * 128 + ty * 8];
            *(float4*)&a[4] = *(float4*)&As[k * 128 + ty * 8 + 4];
            *(float4*)&b[0] = *(float4*)&Bs[k * 128 + tx * 8];
            *(float4*)&b[4] = *(float4*)&Bs[k * 128 + tx * 8 + 4];
#pragma unroll
            for (int i = 0; i < 8; i++)
#pragma unroll
                for (int j = 0; j < 8; j++) acc[i][j] = fmaf(a[i], b[j], acc[i][j]);
        }
        __syncthreads();
    }

#pragma unroll
    for (int i = 0; i < 8; i++) {
        int m = m0 + ty * 8 + i;
#pragma unroll
        for (int j = 0; j < 8; j++) {
            int n   = n0 + tx * 8 + j;
            float y = acc[i][j] + bias[n];
            size_t idx = (size_t)m * 768 + n;
            if (mode) {
                float mp    = mem[idx];
                float reset = (mp > 1.0f) ? 1.0f : 0.0f;  // spike(mem - THR)
                float mn    = 0.6f * mp + y - reset;      // beta*mem + inp - reset*THR
                mem[idx] = mn;
                spk[idx] = (mn > 1.0f) ? 1.0f : 0.0f;
            } else {
                out[idx] = y;
            }
        }
    }
}

// ---------------------------------------------------------------------------
// attn[bh, i, j] = tf32( SCALE * sum_d Q[i,d] * K[j,d] )  (Q,K binary; counts exact)
__global__ __launch_bounds__(256) void attn_qk_kernel() {
    __shared__ float Qs[64 * 64];  // [d][i]
    __shared__ float Ks[64 * 64];  // [d][j]

    const int bh = blockIdx.z;
    const int b  = bh / H_;
    const int h  = bh - b * H_;
    const float* Q = g_spk[0] + (size_t)b * C_ * D_ + h * DH;
    const float* K = g_spk[1] + (size_t)b * C_ * D_ + h * DH;
    const int i0 = blockIdx.y * 64, j0 = blockIdx.x * 64;
    const int t = threadIdx.x;

#pragma unroll
    for (int r = 0; r < 4; r++) {
        int id = t + 256 * r;
        int row = id >> 4, seg = id & 15;
        float4 qa = *(const float4*)&Q[(size_t)(i0 + row) * 768 + seg * 4];
        Qs[(seg * 4 + 0) * 64 + row] = qa.x;
        Qs[(seg * 4 + 1) * 64 + row] = qa.y;
        Qs[(seg * 4 + 2) * 64 + row] = qa.z;
        Qs[(seg * 4 + 3) * 64 + row] = qa.w;
        float4 ka = *(const float4*)&K[(size_t)(j0 + row) * 768 + seg * 4];
        Ks[(seg * 4 + 0) * 64 + row] = ka.x;
        Ks[(seg * 4 + 1) * 64 + row] = ka.y;
        Ks[(seg * 4 + 2) * 64 + row] = ka.z;
        Ks[(seg * 4 + 3) * 64 + row] = ka.w;
    }
    __syncthreads();

    const int ty = t >> 4, tx = t & 15;
    float acc[4][4];
#pragma unroll
    for (int i = 0; i < 4; i++)
#pragma unroll
        for (int j = 0; j < 4; j++) acc[i][j] = 0.0f;

#pragma unroll 16
    for (int d = 0; d < 64; d++) {
        float a[4], bb[4];
        *(float4*)a  = *(float4*)&Qs[d * 64 + ty * 4];
        *(float4*)bb = *(float4*)&Ks[d * 64 + tx * 4];
#pragma unroll
        for (int i = 0; i < 4; i++)
#pragma unroll
            for (int j = 0; j < 4; j++) acc[i][j] = fmaf(a[i], bb[j], acc[i][j]);
    }

    float* outp = g_attn + (size_t)bh * C_ * C_;
#pragma unroll
    for (int i = 0; i < 4; i++) {
        int ii = i0 + ty * 4 + i;
#pragma unroll
        for (int j = 0; j < 4; j++)
            outp[(size_t)ii * 512 + j0 + tx * 4 + j] = tf32r(acc[i][j] * 0.18f);
    }
}

// ---------------------------------------------------------------------------
// x[bh, i, d] = sum_j attn_tf32[i,j] * V[j,d]  then fused LIF -> g_spk[3]
__global__ __launch_bounds__(256) void attn_pv_lif_kernel() {
    __shared__ float As[32 * 64];  // [j][i]
    __shared__ float Vs[32 * 64];  // [j][d]

    const int bh = blockIdx.y;
    const int b  = bh / H_;
    const int h  = bh - b * H_;
    const int i0 = blockIdx.x * 64;
    const float* A = g_attn + (size_t)bh * C_ * C_;
    const float* V = g_spk[2] + (size_t)b * C_ * D_ + h * DH;
    const int t = threadIdx.x, ty = t >> 4, tx = t & 15;

    float acc[4][4];
#pragma unroll
    for (int i = 0; i < 4; i++)
#pragma unroll
        for (int j = 0; j < 4; j++) acc[i][j] = 0.0f;

    for (int kt = 0; kt < 512; kt += 32) {
#pragma unroll
        for (int r = 0; r < 2; r++) {
            int id = t + 256 * r;
            int row = id >> 3, seg = id & 7;
            float4 aa = *(const float4*)&A[(size_t)(i0 + row) * 512 + kt + seg * 4];
            As[(seg * 4 + 0) * 64 + row] = aa.x;
            As[(seg * 4 + 1) * 64 + row] = aa.y;
            As[(seg * 4 + 2) * 64 + row] = aa.z;
            As[(seg * 4 + 3) * 64 + row] = aa.w;
            int vrow = id >> 4, vseg = id & 15;
            float4 vv = *(const float4*)&V[(size_t)(kt + vrow) * 768 + vseg * 4];
            *(float4*)&Vs[vrow * 64 + vseg * 4] = vv;
        }
        __syncthreads();
#pragma unroll
        for (int k = 0; k < 32; k++) {
            float a[4], bb[4];
            *(float4*)a  = *(float4*)&As[k * 64 + ty * 4];
            *(float4*)bb = *(float4*)&Vs[k * 64 + tx * 4];
#pragma unroll
            for (int i = 0; i < 4; i++)
#pragma unroll
                for (int j = 0; j < 4; j++) acc[i][j] = fmaf(a[i], bb[j], acc[i][j]);
        }
        __syncthreads();
    }

    float* mem = g_mem[3];
    float* spk = g_spk[3];
#pragma unroll
    for (int i = 0; i < 4; i++) {
#pragma unroll
        for (int j = 0; j < 4; j++) {
            size_t idx = (size_t)(b * C_ + i0 + ty * 4 + i) * 768 + h * DH + tx * 4 + j;
            float mp    = mem[idx];
            float reset = (mp > 1.0f) ? 1.0f : 0.0f;
            float mn    = 0.6f * mp + acc[i][j] - reset;
            mem[idx] = mn;
            spk[idx] = (mn > 1.0f) ? 1.0f : 0.0f;
        }
    }
}

// ---------------------------------------------------------------------------
// BatchNorm: two-pass stats (matches jnp two-pass var), fp64 accumulation.
__global__ void bn_sum1_kernel() {
    __shared__ double s1[256];
    const int ch = blockIdx.x * 128 + (threadIdx.x & 127);
    const int rg = threadIdx.x >> 7;
    const int r0 = blockIdx.y * 512;
    double s = 0.0;
    for (int r = r0 + rg; r < r0 + 512; r += 2)
        s += (double)g_x2[(size_t)r * 768 + ch];
    s1[threadIdx.x] = s;
    __syncthreads();
    if (rg == 0)
        g_psumd[blockIdx.y * 768 + ch] = s + s1[threadIdx.x + 128];
}

__global__ void bn_mean_kernel() {
    int ch = blockIdx.x * blockDim.x + threadIdx.x;
    if (ch < 768) {
        double s = 0.0;
#pragma unroll
        for (int p = 0; p < 8; p++) s += g_psumd[p * 768 + ch];
        g_mean[ch] = (float)(s * (1.0 / 4096.0));
    }
}

__global__ void bn_var1_kernel() {
    __shared__ double s1[256];
    const int ch = blockIdx.x * 128 + (threadIdx.x & 127);
    const int rg = threadIdx.x >> 7;
    const int r0 = blockIdx.y * 512;
    const float m = g_mean[ch];
    double s = 0.0;
    for (int r = r0 + rg; r < r0 + 512; r += 2) {
        float d = g_x2[(size_t)r * 768 + ch] - m;
        s += (double)d * (double)d;
    }
    s1[threadIdx.x] = s;
    __syncthreads();
    if (rg == 0)
        g_pvard[blockIdx.y * 768 + ch] = s + s1[threadIdx.x + 128];
}

__global__ void bn_var2_kernel() {
    int ch = blockIdx.x * blockDim.x + threadIdx.x;
    if (ch < 768) {
        double s = 0.0;
#pragma unroll
        for (int p = 0; p < 8; p++) s += g_pvard[p * 768 + ch];
        float var = (float)(s * (1.0 / 4096.0));
        g_rstd[ch] = rsqrtf(var + 1e-5f);
    }
}

// BN apply + final LIF -> write spike directly to output att[t]
__global__ void bn_apply_lif_kernel(const float* __restrict__ bnw,
                                    const float* __restrict__ bnb,
                                    float* __restrict__ outp) {
    size_t i = (size_t)blockIdx.x * blockDim.x + threadIdx.x;  // exact grid = BCD
    int ch = (int)(i % 768);
    float x   = g_x2[i];
    float cur = (x - g_mean[ch]) * g_rstd[ch] * bnw[ch] + bnb[ch];
    float mp    = g_mem[4][i];
    float reset = (mp > 1.0f) ? 1.0f : 0.0f;
    float mn    = 0.6f * mp + cur - reset;
    g_mem[4][i] = mn;
    outp[i] = (mn > 1.0f) ? 1.0f : 0.0f;
}

// ---------------------------------------------------------------------------
extern "C" void kernel_launch(void* const* d_in, const int* in_sizes, int n_in,
                              void* d_out, int out_size) {
    (void)in_sizes; (void)n_in; (void)out_size;
    const float* q   = (const float*)d_in[0];
    const float* k   = (const float*)d_in[1];
    const float* v   = (const float*)d_in[2];
    const float* qw  = (const float*)d_in[3];
    const float* qb  = (const float*)d_in[4];
    const float* kw  = (const float*)d_in[5];
    const float* kb  = (const float*)d_in[6];
    const float* vw  = (const float*)d_in[7];
    const float* vb  = (const float*)d_in[8];
    const float* pw  = (const float*)d_in[9];
    const float* pb  = (const float*)d_in[10];
    const float* bnw = (const float*)d_in[11];
    const float* bnb = (const float*)d_in[12];
    float* out = (float*)d_out;

    zero_mem_kernel<<<2048, 256>>>();
    vout_copy_kernel<<<12288, 256>>>(v, out + (size_t)T_ * BCD);

    for (int t = 0; t < T_; t++) {
        const float* qt = q + (size_t)t * BCD;
        const float* kt = k + (size_t)t * BCD;
        const float* vt = v + (size_t)t * BCD;

        dense_gemm_lif<<<dim3(6, 32, 3), 256>>>(qt, kt, vt, qw, kw, vw, qb, kb, vb, 1);
        attn_qk_kernel<<<dim3(8, 8, 96), 256>>>();
        attn_pv_lif_kernel<<<dim3(8, 96), 256>>>();
        dense_gemm_lif<<<dim3(6, 32, 1), 256>>>(nullptr, nullptr, nullptr,
                                                pw, nullptr, nullptr,
                                                pb, nullptr, nullptr, 0);
        bn_sum1_kernel<<<dim3(6, 8), 256>>>();
        bn_mean_kernel<<<3, 256>>>();
        bn_var1_kernel<<<dim3(6, 8), 256>>>();
        bn_var2_kernel<<<3, 256>>>();
        bn_apply_lif_kernel<<<12288, 256>>>(bnw, bnb, out + (size_t)t * BCD);
    }
}

// round 4
// speedup vs baseline: 1.6910x; 1.6910x over previous
#include <cuda_runtime.h>

typedef unsigned long long u64;
typedef unsigned int u32;

// Problem constants
#define T_  4
#define B_  8
#define C_  512
#define D_  768
#define H_  12
#define DH  64
#define BC  (B_*C_)          // 4096
#define BCD (BC*D_)          // 3145728

// Persistent scratch (allocation-free: __device__ globals)
__device__ float  g_mem[5][BCD];      // memq, memk, memv, mematt, mproj
__device__ float  g_spk[4][BCD];      // [2]=sv, [3]=satt (0,1 unused as floats)
__device__ float  g_x2[BCD];          // projection output (pre-BN)
__device__ u64    g_qb[BC * H_];      // packed Q spikes: [b*512+c][h] -> 64 bits (d)
__device__ u64    g_kb[BC * H_];      // packed K spikes
__device__ double g_psumd[8 * D_];
__device__ double g_pvard[8 * D_];
__device__ float  g_mean[D_];
__device__ float  g_rstd[D_];

// ---------------------------------------------------------------------------
__device__ __forceinline__ float tf32r(float x) {
    unsigned u;
    asm("cvt.rna.tf32.f32 %0, %1;" : "=r"(u) : "f"(x));
    return __uint_as_float(u);
}

// f32x2 packed FMA helpers (compiled OK on sm_103 in R3)
__device__ __forceinline__ u64 bcast2(float a) {
    u64 r; asm("mov.b64 %0, {%1, %1};" : "=l"(r) : "f"(a)); return r;
}
__device__ __forceinline__ void fma2(u64& acc, u64 a, u64 b) {
    asm("fma.rn.f32x2 %0, %1, %2, %0;" : "+l"(acc) : "l"(a), "l"(b));
}
__device__ __forceinline__ float2 unpack2(u64 v) {
    float2 f; asm("mov.b64 {%0, %1}, %2;" : "=f"(f.x), "=f"(f.y) : "l"(v)); return f;
}

// mma.sync m16n8k8 tf32 (fallback HMMA on sm_103 — plain PTX, no 'a' gate)
__device__ __forceinline__ void mma_tf32(float* d, const u32* a, const u32* b) {
    asm volatile(
        "mma.sync.aligned.m16n8k8.row.col.f32.tf32.tf32.f32 "
        "{%0,%1,%2,%3}, {%4,%5,%6,%7}, {%8,%9}, {%0,%1,%2,%3};"
        : "+f"(d[0]), "+f"(d[1]), "+f"(d[2]), "+f"(d[3])
        : "r"(a[0]), "r"(a[1]), "r"(a[2]), "r"(a[3]), "r"(b[0]), "r"(b[1]));
}

// ---------------------------------------------------------------------------
__global__ void zero_mem_kernel() {
    size_t n = (size_t)5 * BCD;
    float* p = &g_mem[0][0];
    for (size_t i = (size_t)blockIdx.x * blockDim.x + threadIdx.x; i < n;
         i += (size_t)gridDim.x * blockDim.x)
        p[i] = 0.0f;
}

__global__ void vout_copy_kernel(const float* __restrict__ v, float* __restrict__ o) {
    const size_t n4 = (size_t)T_ * BCD / 4;
    size_t i = (size_t)blockIdx.x * blockDim.x + threadIdx.x;
    if (i < n4) {
        float4 val = ((const float4*)v)[i];
        float4* o4 = (float4*)o;
        o4[i]          = val;
        o4[i + n4]     = val;
        o4[i + 2 * n4] = val;
        o4[i + 3 * n4] = val;
    }
}

// ---------------------------------------------------------------------------
// Dense TF32 GEMM on tensor cores (mma.sync): D[m,n] = sum_k tf32(X[m,k])*tf32(W[n,k])
// CTA tile 128x128, BK=32. 8 warps in 2(m)x4(n), warp tile 64x32 (4x4 m16n8k8 atoms).
// Smem: As[128][36], Bs[128][36] (row-major, pad->conflict-free frag loads: 36%32=4,
// frag addr = 36*g + c -> bank 4g+c distinct). Epilogue stages via smem in 2 row-halves.
// mode 1: q/k/v projection + LIF; z=0/1 -> bitpacked spikes (g_qb/g_kb), z=2 -> g_spk[2]
// mode 0: output projection (X=g_spk[3], W=pw) -> g_x2
#define SM_FLOATS (2 * 128 * 36)   // 9216 floats = 36864 B

__global__ __launch_bounds__(256, 2) void dense_mma_gemm(
    const float* __restrict__ Xq, const float* __restrict__ Xk, const float* __restrict__ Xv,
    const float* __restrict__ Wq, const float* __restrict__ Wk, const float* __restrict__ Wv,
    const float* __restrict__ bq, const float* __restrict__ bk, const float* __restrict__ bv,
    int mode)
{
    __shared__ float sm[SM_FLOATS];
    float* As = sm;                 // [128][36]
    float* Bs = sm + 128 * 36;      // [128][36]
    const u32* Asu = (const u32*)As;
    const u32* Bsu = (const u32*)Bs;

    const int z = blockIdx.z;
    const float* X;
    const float* W;
    const float* bias;
    float* mem = nullptr;
    float* spk = nullptr;
    float* out = nullptr;
    u32*   bitout = nullptr;
    if (mode) {
        X    = (z == 0) ? Xq : ((z == 1) ? Xk : Xv);
        W    = (z == 0) ? Wq : ((z == 1) ? Wk : Wv);
        bias = (z == 0) ? bq : ((z == 1) ? bk : bv);
        mem  = g_mem[z];
        if (z == 2) spk = g_spk[2];
        else bitout = (z == 0) ? (u32*)g_qb : (u32*)g_kb;
    } else {
        X = g_spk[3]; W = Wq; bias = bq; out = g_x2;
    }

    const int tid  = threadIdx.x;
    const int wid  = tid >> 5, lane = tid & 31;
    const int g    = lane >> 2, c = lane & 3;     // mma groupID / threadID-in-group
    const int wm   = wid & 1;                      // warp m position (0..1) * 64
    const int wn   = wid >> 1;                     // warp n position (0..3) * 32
    const int m0   = blockIdx.y * 128;
    const int n0   = blockIdx.x * 128;

    float acc[4][4][4];
#pragma unroll
    for (int im = 0; im < 4; im++)
#pragma unroll
        for (int in = 0; in < 4; in++)
#pragma unroll
            for (int r = 0; r < 4; r++) acc[im][in][r] = 0.0f;

    for (int chunk = 0; chunk < 24; chunk++) {
        const int k0 = chunk * 32;
        __syncthreads();
        // Load tiles: 128 rows x 32 k each, coalesced LDG (8 lanes per row), .128 STS
#pragma unroll
        for (int pass = 0; pass < 4; pass++) {
            int id  = tid + pass * 256;
            int row = id >> 3, seg = id & 7;
            float4 xa = *(const float4*)&X[(size_t)(m0 + row) * 768 + k0 + seg * 4];
            *(float4*)&As[row * 36 + seg * 4] =
                make_float4(tf32r(xa.x), tf32r(xa.y), tf32r(xa.z), tf32r(xa.w));
            float4 wb = *(const float4*)&W[(size_t)(n0 + row) * 768 + k0 + seg * 4];
            *(float4*)&Bs[row * 36 + seg * 4] =
                make_float4(tf32r(wb.x), tf32r(wb.y), tf32r(wb.z), tf32r(wb.w));
        }
        __syncthreads();

#pragma unroll
        for (int ka = 0; ka < 4; ka++) {
            const int kk = ka * 8;
            u32 a[4][4], b[4][2];
#pragma unroll
            for (int im = 0; im < 4; im++) {
                int row = wm * 64 + im * 16 + g;
                a[im][0] = Asu[row * 36 + kk + c];
                a[im][1] = Asu[(row + 8) * 36 + kk + c];
                a[im][2] = Asu[row * 36 + kk + c + 4];
                a[im][3] = Asu[(row + 8) * 36 + kk + c + 4];
            }
#pragma unroll
            for (int in = 0; in < 4; in++) {
                int nn = wn * 32 + in * 8 + g;
                b[in][0] = Bsu[nn * 36 + kk + c];
                b[in][1] = Bsu[nn * 36 + kk + c + 4];
            }
#pragma unroll
            for (int im = 0; im < 4; im++)
#pragma unroll
                for (int in = 0; in < 4; in++)
                    mma_tf32(acc[im][in], a[im], b[in]);
        }
    }

    // Epilogue: stage 64-row halves in smem, then coalesced bias+LIF+store.
    float* sE = sm;   // [64][132] = 8448 floats <= 9216
#pragma unroll
    for (int p = 0; p < 2; p++) {
        __syncthreads();
        if (wm == p) {
#pragma unroll
            for (int im = 0; im < 4; im++)
#pragma unroll
                for (int in = 0; in < 4; in++) {
                    int rr   = im * 16 + g;
                    int colb = wn * 32 + in * 8 + 2 * c;
                    sE[rr * 132 + colb]           = acc[im][in][0];
                    sE[rr * 132 + colb + 1]       = acc[im][in][1];
                    sE[(rr + 8) * 132 + colb]     = acc[im][in][2];
                    sE[(rr + 8) * 132 + colb + 1] = acc[im][in][3];
                }
        }
        __syncthreads();
        const int nc = wid & 3;        // n chunk of 32
        const int rh = wid >> 2;       // row half of 32
        const int nn = n0 + nc * 32 + lane;
        const float bvv = bias[nn];
        const int head = nn >> 6, half = (nn >> 5) & 1;
        for (int rr = rh * 32; rr < rh * 32 + 32; rr++) {
            float y = sE[rr * 132 + nc * 32 + lane] + bvv;
            int m = m0 + p * 64 + rr;
            size_t idx = (size_t)m * 768 + nn;
            if (mode) {
                float mp    = mem[idx];
                float reset = (mp > 1.0f) ? 1.0f : 0.0f;
                float mn    = 0.6f * mp + y - reset;
                mem[idx] = mn;
                float sp = (mn > 1.0f) ? 1.0f : 0.0f;
                if (z == 2) {
                    spk[idx] = sp;
                } else {
                    u32 bits = __ballot_sync(0xffffffffu, sp > 0.5f);
                    if (lane == 0) bitout[(m * H_ + head) * 2 + half] = bits;
                }
            } else {
                out[idx] = y;
            }
        }
    }
}

// ---------------------------------------------------------------------------
// Fused attention: per (b,h, i-tile 64): S = tf32(0.18*popc(q&k)); X = S @ V; LIF.
__global__ __launch_bounds__(256) void attn_fused_kernel() {
    __shared__ u64   Qb[64];
    __shared__ u64   Kb[512];
    __shared__ float Ss[64 * 64];   // [i][j]
    __shared__ float Vs[64 * 64];   // [j][d]

    const int bh = blockIdx.y;
    const int b  = bh / H_;
    const int h  = bh - b * H_;
    const int i0 = blockIdx.x * 64;
    const int tid = threadIdx.x;
    const int ty = tid >> 4, tx = tid & 15;

    if (tid < 64) Qb[tid] = g_qb[(size_t)(b * C_ + i0 + tid) * H_ + h];
    Kb[tid]       = g_kb[(size_t)(b * C_ + tid) * H_ + h];
    Kb[tid + 256] = g_kb[(size_t)(b * C_ + tid + 256) * H_ + h];
    __syncthreads();

    const float* V = g_spk[2] + (size_t)b * C_ * D_ + h * DH;

    u64 acc[4][2];
#pragma unroll
    for (int i = 0; i < 4; i++) { acc[i][0] = 0ull; acc[i][1] = 0ull; }

    for (int jt = 0; jt < 8; jt++) {
        const int j0 = jt * 64;
#pragma unroll
        for (int r = 0; r < 16; r++) {
            int id = tid * 16 + r;
            int i = id >> 6, j = id & 63;
            Ss[i * 64 + j] = tf32r(0.18f * (float)__popcll(Qb[i] & Kb[j0 + j]));
        }
#pragma unroll
        for (int r = 0; r < 4; r++) {
            int id = tid + 256 * r;
            int j = id >> 4, seg = id & 15;
            *(float4*)&Vs[j * 64 + seg * 4] =
                *(const float4*)&V[(size_t)(j0 + j) * 768 + seg * 4];
        }
        __syncthreads();
#pragma unroll 4
        for (int k = 0; k < 64; k++) {
            u64 v0 = *(const u64*)&Vs[k * 64 + tx * 4];
            u64 v1 = *(const u64*)&Vs[k * 64 + tx * 4 + 2];
#pragma unroll
            for (int ii = 0; ii < 4; ii++) {
                u64 a = bcast2(Ss[(ty * 4 + ii) * 64 + k]);
                fma2(acc[ii][0], a, v0);
                fma2(acc[ii][1], a, v1);
            }
        }
        __syncthreads();
    }

    float* mem = g_mem[3];
    float* spk = g_spk[3];
#pragma unroll
    for (int ii = 0; ii < 4; ii++) {
        float2 lo = unpack2(acc[ii][0]);
        float2 hi = unpack2(acc[ii][1]);
        float xv[4] = {lo.x, lo.y, hi.x, hi.y};
        size_t base = (size_t)(b * C_ + i0 + ty * 4 + ii) * 768 + h * DH + tx * 4;
#pragma unroll
        for (int j = 0; j < 4; j++) {
            size_t idx = base + j;
            float mp    = mem[idx];
            float reset = (mp > 1.0f) ? 1.0f : 0.0f;
            float mn    = 0.6f * mp + xv[j] - reset;
            mem[idx] = mn;
            spk[idx] = (mn > 1.0f) ? 1.0f : 0.0f;
        }
    }
}

// ---------------------------------------------------------------------------
// BatchNorm: two-pass stats (matches jnp two-pass var), fp64 accumulation.
__global__ void bn_sum1_kernel() {
    __shared__ double s1[256];
    const int ch = blockIdx.x * 128 + (threadIdx.x & 127);
    const int rg = threadIdx.x >> 7;
    const int r0 = blockIdx.y * 512;
    double s = 0.0;
    for (int r = r0 + rg; r < r0 + 512; r += 2)
        s += (double)g_x2[(size_t)r * 768 + ch];
    s1[threadIdx.x] = s;
    __syncthreads();
    if (rg == 0)
        g_psumd[blockIdx.y * 768 + ch] = s + s1[threadIdx.x + 128];
}

__global__ void bn_mean_kernel() {
    int ch = blockIdx.x * blockDim.x + threadIdx.x;
    if (ch < 768) {
        double s = 0.0;
#pragma unroll
        for (int p = 0; p < 8; p++) s += g_psumd[p * 768 + ch];
        g_mean[ch] = (float)(s * (1.0 / 4096.0));
    }
}

__global__ void bn_var1_kernel() {
    __shared__ double s1[256];
    const int ch = blockIdx.x * 128 + (threadIdx.x & 127);
    const int rg = threadIdx.x >> 7;
    const int r0 = blockIdx.y * 512;
    const float m = g_mean[ch];
    double s = 0.0;
    for (int r = r0 + rg; r < r0 + 512; r += 2) {
        float d = g_x2[(size_t)r * 768 + ch] - m;
        s += (double)d * (double)d;
    }
    s1[threadIdx.x] = s;
    __syncthreads();
    if (rg == 0)
        g_pvard[blockIdx.y * 768 + ch] = s + s1[threadIdx.x + 128];
}

__global__ void bn_var2_kernel() {
    int ch = blockIdx.x * blockDim.x + threadIdx.x;
    if (ch < 768) {
        double s = 0.0;
#pragma unroll
        for (int p = 0; p < 8; p++) s += g_pvard[p * 768 + ch];
        float var = (float)(s * (1.0 / 4096.0));
        g_rstd[ch] = rsqrtf(var + 1e-5f);
    }
}

__global__ void bn_apply_lif_kernel(const float* __restrict__ bnw,
                                    const float* __restrict__ bnb,
                                    float* __restrict__ outp) {
    size_t i = (size_t)blockIdx.x * blockDim.x + threadIdx.x;
    int ch = (int)(i % 768);
    float x   = g_x2[i];
    float cur = (x - g_mean[ch]) * g_rstd[ch] * bnw[ch] + bnb[ch];
    float mp    = g_mem[4][i];
    float reset = (mp > 1.0f) ? 1.0f : 0.0f;
    float mn    = 0.6f * mp + cur - reset;
    g_mem[4][i] = mn;
    outp[i] = (mn > 1.0f) ? 1.0f : 0.0f;
}

// ---------------------------------------------------------------------------
extern "C" void kernel_launch(void* const* d_in, const int* in_sizes, int n_in,
                              void* d_out, int out_size) {
    (void)in_sizes; (void)n_in; (void)out_size;
    const float* q   = (const float*)d_in[0];
    const float* k   = (const float*)d_in[1];
    const float* v   = (const float*)d_in[2];
    const float* qw  = (const float*)d_in[3];
    const float* qb  = (const float*)d_in[4];
    const float* kw  = (const float*)d_in[5];
    const float* kb  = (const float*)d_in[6];
    const float* vw  = (const float*)d_in[7];
    const float* vb  = (const float*)d_in[8];
    const float* pw  = (const float*)d_in[9];
    const float* pb  = (const float*)d_in[10];
    const float* bnw = (const float*)d_in[11];
    const float* bnb = (const float*)d_in[12];
    float* out = (float*)d_out;

    zero_mem_kernel<<<2048, 256>>>();
    vout_copy_kernel<<<12288, 256>>>(v, out + (size_t)T_ * BCD);

    for (int t = 0; t < T_; t++) {
        const float* qt = q + (size_t)t * BCD;
        const float* kt = k + (size_t)t * BCD;
        const float* vt = v + (size_t)t * BCD;

        // q/k/v projections + LIF (tensor-core TF32), writes Q/K bitpacks + V spikes
        dense_mma_gemm<<<dim3(6, 32, 3), 256>>>(qt, kt, vt, qw, kw, vw, qb, kb, vb, 1);
        // fused attention (popcount QK + f32x2 PV) + LIF -> satt
        attn_fused_kernel<<<dim3(8, 96), 256>>>();
        // output projection (tensor-core TF32) -> g_x2
        dense_mma_gemm<<<dim3(6, 32, 1), 256>>>(nullptr, nullptr, nullptr,
                                                pw, nullptr, nullptr,
                                                pb, nullptr, nullptr, 0);
        // BatchNorm (two-pass, fp64) + final LIF -> att[t]
        bn_sum1_kernel<<<dim3(6, 8), 256>>>();
        bn_mean_kernel<<<3, 256>>>();
        bn_var1_kernel<<<dim3(6, 8), 256>>>();
        bn_var2_kernel<<<3, 256>>>();
        bn_apply_lif_kernel<<<12288, 256>>>(bnw, bnb, out + (size_t)t * BCD);
    }
}

// round 6
// speedup vs baseline: 2.6417x; 1.5622x over previous
#include <cuda_runtime.h>

typedef unsigned long long u64;
typedef unsigned int u32;

// Problem constants
#define T_  4
#define B_  8
#define C_  512
#define D_  768
#define H_  12
#define DH  64
#define BC  (B_*C_)          // 4096
#define BCD (BC*D_)          // 3145728

// Persistent scratch (allocation-free: __device__ globals)
__device__ float  g_mem[5][BCD];      // memq, memk, memv, mematt, mproj
__device__ float  g_spk2[BCD];        // sv (binary floats)
__device__ float  g_spk3[BCD];        // satt (binary floats)
__device__ float  g_x2[BCD];          // projection output (pre-BN)
__device__ u64    g_qb[BC * H_];      // packed Q spikes
__device__ u64    g_kb[BC * H_];      // packed K spikes
__device__ float  g_cq[T_ * BCD];     // tf32-preconverted inputs
__device__ float  g_ck[T_ * BCD];
__device__ float  g_cv[T_ * BCD];
__device__ float  g_wc[4][D_ * D_];   // tf32-preconverted weights qw,kw,vw,pw
__device__ double g_psumd[8 * D_];
__device__ double g_pvard[8 * D_];
__device__ float  g_mean[D_];
__device__ float  g_rstd[D_];

// ---------------------------------------------------------------------------
__device__ __forceinline__ float tf32r(float x) {
    unsigned u;
    asm("cvt.rna.tf32.f32 %0, %1;" : "=r"(u) : "f"(x));
    return __uint_as_float(u);
}
__device__ __forceinline__ u32 smem_u32(const void* p) {
    u32 a;
    asm("{ .reg .u64 t; cvta.to.shared.u64 t, %1; cvt.u32.u64 %0, t; }" : "=r"(a) : "l"(p));
    return a;
}
// cp.async (plain sm_80 PTX, no arch-suffix gate)
#define CP_ASYNC16(saddr, gptr) \
    asm volatile("cp.async.ca.shared.global [%0], [%1], 16;" :: "r"(saddr), "l"(gptr))
#define CP_COMMIT() asm volatile("cp.async.commit_group;" ::: "memory")
#define CP_WAIT(n)  asm volatile("cp.async.wait_group %0;" :: "n"(n) : "memory")

// mma.sync m16n8k8 tf32 (fallback HMMA; proven rel_err=0.0 in R4)
__device__ __forceinline__ void mma_tf32(float* d, const u32* a, const u32* b) {
    asm volatile(
        "mma.sync.aligned.m16n8k8.row.col.f32.tf32.tf32.f32 "
        "{%0,%1,%2,%3}, {%4,%5,%6,%7}, {%8,%9}, {%0,%1,%2,%3};"
        : "+f"(d[0]), "+f"(d[1]), "+f"(d[2]), "+f"(d[3])
        : "r"(a[0]), "r"(a[1]), "r"(a[2]), "r"(a[3]), "r"(b[0]), "r"(b[1]));
}

// ---------------------------------------------------------------------------
__global__ void zero_mem_kernel() {
    size_t n = (size_t)5 * BCD;
    float* p = &g_mem[0][0];
    for (size_t i = (size_t)blockIdx.x * blockDim.x + threadIdx.x; i < n;
         i += (size_t)gridDim.x * blockDim.x)
        p[i] = 0.0f;
}

__global__ void vout_copy_kernel(const float* __restrict__ v, float* __restrict__ o) {
    const size_t n4 = (size_t)T_ * BCD / 4;
    size_t i = (size_t)blockIdx.x * blockDim.x + threadIdx.x;
    if (i < n4) {
        float4 val = ((const float4*)v)[i];
        float4* o4 = (float4*)o;
        o4[i]          = val;
        o4[i + n4]     = val;
        o4[i + 2 * n4] = val;
        o4[i + 3 * n4] = val;
    }
}

// Pre-convert an array to tf32 (RNA), float4-vectorized.
__global__ void cvt_tf32_kernel(const float4* __restrict__ src, float4* __restrict__ dst,
                                int n4) {
    int i = blockIdx.x * blockDim.x + threadIdx.x;
    if (i < n4) {
        float4 v = src[i];
        dst[i] = make_float4(tf32r(v.x), tf32r(v.y), tf32r(v.z), tf32r(v.w));
    }
}

// ---------------------------------------------------------------------------
// Dense TF32 GEMM on tensor cores, cp.async double-buffered.
// Inputs are PRE-CONVERTED to tf32 (or binary spikes = tf32-exact).
// CTA tile 128x128, BK=32, 8 warps 2(m)x4(n), warp tile 64x32.
#define DSM_BYTES (2 * 2 * 128 * 36 * 4)

__global__ __launch_bounds__(256, 2) void dense_mma_gemm(
    const float* __restrict__ Xq, const float* __restrict__ Xk, const float* __restrict__ Xv,
    const float* __restrict__ Wq, const float* __restrict__ Wk, const float* __restrict__ Wv,
    const float* __restrict__ bq, const float* __restrict__ bk, const float* __restrict__ bv,
    int mode)
{
    extern __shared__ char dsm[];
    const u32 sb = smem_u32(dsm);

    const int z = blockIdx.z;
    const float* X;
    const float* W;
    const float* bias;
    float* mem = nullptr;
    float* spk = nullptr;
    float* out = nullptr;
    u32*   bitout = nullptr;
    if (mode) {
        X    = (z == 0) ? Xq : ((z == 1) ? Xk : Xv);
        W    = (z == 0) ? Wq : ((z == 1) ? Wk : Wv);
        bias = (z == 0) ? bq : ((z == 1) ? bk : bv);
        mem  = g_mem[z];
        if (z == 2) spk = g_spk2;
        else bitout = (z == 0) ? (u32*)g_qb : (u32*)g_kb;
    } else {
        X = g_spk3; W = Wq; bias = bq; out = g_x2;
    }

    const int tid  = threadIdx.x;
    const int wid  = tid >> 5, lane = tid & 31;
    const int g    = lane >> 2, c = lane & 3;
    const int wm   = wid & 1;
    const int wn   = wid >> 1;
    const int m0   = blockIdx.y * 128;
    const int n0   = blockIdx.x * 128;

    float acc[4][4][4];
#pragma unroll
    for (int im = 0; im < 4; im++)
#pragma unroll
        for (int in = 0; in < 4; in++)
#pragma unroll
            for (int r = 0; r < 4; r++) acc[im][in][r] = 0.0f;

    const int row = tid >> 3, seg = tid & 7;   // loader mapping

    auto issue_stage = [&](int buf, int chunk) {
        const int k0 = chunk * 32;
        const u32 sA = sb + buf * 36864;
        const u32 sB = sA + 18432;
#pragma unroll
        for (int pass = 0; pass < 4; pass++) {
            int rr = row + pass * 32;
            u32 off = (u32)((rr * 36 + seg * 4) * 4);
            CP_ASYNC16(sA + off, &X[(size_t)(m0 + rr) * 768 + k0 + seg * 4]);
            CP_ASYNC16(sB + off, &W[(size_t)(n0 + rr) * 768 + k0 + seg * 4]);
        }
    };

    issue_stage(0, 0);
    CP_COMMIT();

    for (int chunk = 0; chunk < 24; chunk++) {
        if (chunk + 1 < 24) {
            issue_stage((chunk + 1) & 1, chunk + 1);
            CP_COMMIT();
            CP_WAIT(1);
        } else {
            CP_WAIT(0);
        }
        __syncthreads();

        const u32* Asu = (const u32*)(dsm + (chunk & 1) * 36864);
        const u32* Bsu = (const u32*)(dsm + (chunk & 1) * 36864 + 18432);
#pragma unroll
        for (int ka = 0; ka < 4; ka++) {
            const int kk = ka * 8;
            u32 a[4][4], b[4][2];
#pragma unroll
            for (int im = 0; im < 4; im++) {
                int r = wm * 64 + im * 16 + g;
                a[im][0] = Asu[r * 36 + kk + c];
                a[im][1] = Asu[(r + 8) * 36 + kk + c];
                a[im][2] = Asu[r * 36 + kk + c + 4];
                a[im][3] = Asu[(r + 8) * 36 + kk + c + 4];
            }
#pragma unroll
            for (int in = 0; in < 4; in++) {
                int nn = wn * 32 + in * 8 + g;
                b[in][0] = Bsu[nn * 36 + kk + c];
                b[in][1] = Bsu[nn * 36 + kk + c + 4];
            }
#pragma unroll
            for (int im = 0; im < 4; im++)
#pragma unroll
                for (int in = 0; in < 4; in++)
                    mma_tf32(acc[im][in], a[im], b[in]);
        }
        __syncthreads();
    }

    // Epilogue: stage 64-row halves in smem, coalesced bias+LIF+store.
    float* sE = (float*)dsm;   // [64][132] = 8448 floats (fits buffer 0)
#pragma unroll
    for (int p = 0; p < 2; p++) {
        __syncthreads();
        if (wm == p) {
#pragma unroll
            for (int im = 0; im < 4; im++)
#pragma unroll
                for (int in = 0; in < 4; in++) {
                    int rr   = im * 16 + g;
                    int colb = wn * 32 + in * 8 + 2 * c;
                    sE[rr * 132 + colb]           = acc[im][in][0];
                    sE[rr * 132 + colb + 1]       = acc[im][in][1];
                    sE[(rr + 8) * 132 + colb]     = acc[im][in][2];
                    sE[(rr + 8) * 132 + colb + 1] = acc[im][in][3];
                }
        }
        __syncthreads();
        const int nc = wid & 3;
        const int rh = wid >> 2;
        const int nn = n0 + nc * 32 + lane;
        const float bvv = bias[nn];
        const int head = nn >> 6, half = (nn >> 5) & 1;
        for (int rr = rh * 32; rr < rh * 32 + 32; rr++) {
            float y = sE[rr * 132 + nc * 32 + lane] + bvv;
            int m = m0 + p * 64 + rr;
            size_t idx = (size_t)m * 768 + nn;
            if (mode) {
                float mp    = mem[idx];
                float reset = (mp > 1.0f) ? 1.0f : 0.0f;
                float mn    = 0.6f * mp + y - reset;
                mem[idx] = mn;
                float sp = (mn > 1.0f) ? 1.0f : 0.0f;
                if (z == 2) {
                    spk[idx] = sp;
                } else {
                    u32 bits = __ballot_sync(0xffffffffu, sp > 0.5f);
                    if (lane == 0) bitout[(m * H_ + head) * 2 + half] = bits;
                }
            } else {
                out[idx] = y;
            }
        }
    }
}

// ---------------------------------------------------------------------------
// Fused attention on tensor cores.
// Per CTA: (b,h, i-tile of 128). X[128,64] = S[128,512] @ V[512,64], LIF -> satt.
// S fragments generated INLINE from bitpacked Q/K popcounts (no S smem).
// V chunk (32j x 64d) transposed into smem [d][36]; FIXED: full 64-d coverage
// (two float4 loads per thread; R5 only wrote d<32 -> garbage upper half).
__global__ __launch_bounds__(256) void attn_mma_kernel() {
    __shared__ u64   Kb[512];
    __shared__ float Vs[64 * 36];

    const int bh = blockIdx.y;
    const int b  = bh / H_;
    const int h  = bh - b * H_;
    const int i0 = blockIdx.x * 128;
    const int tid = threadIdx.x;
    const int wid = tid >> 5, lane = tid & 31;
    const int g = lane >> 2, cc = lane & 3;

    Kb[tid]       = g_kb[(size_t)(b * C_ + tid) * H_ + h];
    Kb[tid + 256] = g_kb[(size_t)(b * C_ + tid + 256) * H_ + h];

    const int irow0 = i0 + wid * 16 + g;
    const u64 q0 = g_qb[(size_t)(b * C_ + irow0) * H_ + h];
    const u64 q1 = g_qb[(size_t)(b * C_ + irow0 + 8) * H_ + h];

    const float* V = g_spk2 + (size_t)b * C_ * D_ + h * DH;

    float acc[8][4];
#pragma unroll
    for (int in = 0; in < 8; in++)
#pragma unroll
        for (int r = 0; r < 4; r++) acc[in][r] = 0.0f;

    // V loader: vj = j row (0..31), vd = d quad (0..7); two float4 per thread
    // covers d = 4*vd..4*vd+3 and d = 32+4*vd..32+4*vd+3  -> all 64 d's.
    const int vj = tid >> 3, vd = tid & 7;
    float4 va = *(const float4*)&V[(size_t)vj * 768 + vd * 4];
    float4 vb = *(const float4*)&V[(size_t)vj * 768 + 32 + vd * 4];
    __syncthreads();   // Kb ready

    const u32* Vsu = (const u32*)Vs;
    for (int c = 0; c < 16; c++) {
        // store staged V chunk (transposed): Vs[d][j]
        Vs[(4 * vd + 0) * 36 + vj] = va.x;
        Vs[(4 * vd + 1) * 36 + vj] = va.y;
        Vs[(4 * vd + 2) * 36 + vj] = va.z;
        Vs[(4 * vd + 3) * 36 + vj] = va.w;
        Vs[(32 + 4 * vd + 0) * 36 + vj] = vb.x;
        Vs[(32 + 4 * vd + 1) * 36 + vj] = vb.y;
        Vs[(32 + 4 * vd + 2) * 36 + vj] = vb.z;
        Vs[(32 + 4 * vd + 3) * 36 + vj] = vb.w;
        __syncthreads();
        if (c < 15) {
            va = *(const float4*)&V[(size_t)((c + 1) * 32 + vj) * 768 + vd * 4];
            vb = *(const float4*)&V[(size_t)((c + 1) * 32 + vj) * 768 + 32 + vd * 4];
        }

#pragma unroll
        for (int ka = 0; ka < 4; ka++) {
            const int jb = c * 32 + ka * 8;
            const u64 kb0 = Kb[jb + cc];
            const u64 kb4 = Kb[jb + cc + 4];
            u32 a[4];
            a[0] = __float_as_uint(tf32r(0.18f * (float)__popcll(q0 & kb0)));
            a[1] = __float_as_uint(tf32r(0.18f * (float)__popcll(q1 & kb0)));
            a[2] = __float_as_uint(tf32r(0.18f * (float)__popcll(q0 & kb4)));
            a[3] = __float_as_uint(tf32r(0.18f * (float)__popcll(q1 & kb4)));
#pragma unroll
            for (int in = 0; in < 8; in++) {
                u32 bfr[2];
                bfr[0] = Vsu[(in * 8 + g) * 36 + ka * 8 + cc];
                bfr[1] = Vsu[(in * 8 + g) * 36 + ka * 8 + cc + 4];
                mma_tf32(acc[in], a, bfr);
            }
        }
        __syncthreads();
    }

    // LIF epilogue -> g_mem[3], g_spk3
    float* mem = g_mem[3];
    float* spk = g_spk3;
#pragma unroll
    for (int in = 0; in < 8; in++) {
        int col = h * DH + in * 8 + 2 * cc;
        size_t idx0 = (size_t)(b * C_ + irow0) * 768 + col;
        size_t idx1 = (size_t)(b * C_ + irow0 + 8) * 768 + col;
#pragma unroll
        for (int e = 0; e < 2; e++) {
            float mp    = mem[idx0 + e];
            float reset = (mp > 1.0f) ? 1.0f : 0.0f;
            float mn    = 0.6f * mp + acc[in][e] - reset;
            mem[idx0 + e] = mn;
            spk[idx0 + e] = (mn > 1.0f) ? 1.0f : 0.0f;
            float mp1    = mem[idx1 + e];
            float reset1 = (mp1 > 1.0f) ? 1.0f : 0.0f;
            float mn1    = 0.6f * mp1 + acc[in][2 + e] - reset1;
            mem[idx1 + e] = mn1;
            spk[idx1 + e] = (mn1 > 1.0f) ? 1.0f : 0.0f;
        }
    }
}

// ---------------------------------------------------------------------------
// BatchNorm: two-pass stats (matches jnp two-pass var), fp64 accumulation.
__global__ void bn_sum1_kernel() {
    __shared__ double s1[256];
    const int ch = blockIdx.x * 128 + (threadIdx.x & 127);
    const int rg = threadIdx.x >> 7;
    const int r0 = blockIdx.y * 512;
    double s = 0.0;
    for (int r = r0 + rg; r < r0 + 512; r += 2)
        s += (double)g_x2[(size_t)r * 768 + ch];
    s1[threadIdx.x] = s;
    __syncthreads();
    if (rg == 0)
        g_psumd[blockIdx.y * 768 + ch] = s + s1[threadIdx.x + 128];
}

__global__ void bn_mean_kernel() {
    int ch = blockIdx.x * blockDim.x + threadIdx.x;
    if (ch < 768) {
        double s = 0.0;
#pragma unroll
        for (int p = 0; p < 8; p++) s += g_psumd[p * 768 + ch];
        g_mean[ch] = (float)(s * (1.0 / 4096.0));
    }
}

__global__ void bn_var1_kernel() {
    __shared__ double s1[256];
    const int ch = blockIdx.x * 128 + (threadIdx.x & 127);
    const int rg = threadIdx.x >> 7;
    const int r0 = blockIdx.y * 512;
    const float m = g_mean[ch];
    double s = 0.0;
    for (int r = r0 + rg; r < r0 + 512; r += 2) {
        float d = g_x2[(size_t)r * 768 + ch] - m;
        s += (double)d * (double)d;
    }
    s1[threadIdx.x] = s;
    __syncthreads();
    if (rg == 0)
        g_pvard[blockIdx.y * 768 + ch] = s + s1[threadIdx.x + 128];
}

__global__ void bn_var2_kernel() {
    int ch = blockIdx.x * blockDim.x + threadIdx.x;
    if (ch < 768) {
        double s = 0.0;
#pragma unroll
        for (int p = 0; p < 8; p++) s += g_pvard[p * 768 + ch];
        float var = (float)(s * (1.0 / 4096.0));
        g_rstd[ch] = rsqrtf(var + 1e-5f);
    }
}

__global__ void bn_apply_lif_kernel(const float* __restrict__ bnw,
                                    const float* __restrict__ bnb,
                                    float* __restrict__ outp) {
    size_t i = (size_t)blockIdx.x * blockDim.x + threadIdx.x;
    int ch = (int)(i % 768);
    float x   = g_x2[i];
    float cur = (x - g_mean[ch]) * g_rstd[ch] * bnw[ch] + bnb[ch];
    float mp    = g_mem[4][i];
    float reset = (mp > 1.0f) ? 1.0f : 0.0f;
    float mn    = 0.6f * mp + cur - reset;
    g_mem[4][i] = mn;
    outp[i] = (mn > 1.0f) ? 1.0f : 0.0f;
}

// ---------------------------------------------------------------------------
extern "C" void kernel_launch(void* const* d_in, const int* in_sizes, int n_in,
                              void* d_out, int out_size) {
    (void)in_sizes; (void)n_in; (void)out_size;
    const float* q   = (const float*)d_in[0];
    const float* k   = (const float*)d_in[1];
    const float* v   = (const float*)d_in[2];
    const float* qw  = (const float*)d_in[3];
    const float* qb  = (const float*)d_in[4];
    const float* kw  = (const float*)d_in[5];
    const float* kb  = (const float*)d_in[6];
    const float* vw  = (const float*)d_in[7];
    const float* vb  = (const float*)d_in[8];
    const float* pw  = (const float*)d_in[9];
    const float* pb  = (const float*)d_in[10];
    const float* bnw = (const float*)d_in[11];
    const float* bnb = (const float*)d_in[12];
    float* out = (float*)d_out;

    cudaFuncSetAttribute(dense_mma_gemm, cudaFuncAttributeMaxDynamicSharedMemorySize,
                         DSM_BYTES);

    float* cq; cudaGetSymbolAddress((void**)&cq, g_cq);
    float* ck; cudaGetSymbolAddress((void**)&ck, g_ck);
    float* cv; cudaGetSymbolAddress((void**)&cv, g_cv);
    float* wc; cudaGetSymbolAddress((void**)&wc, g_wc);

    zero_mem_kernel<<<2048, 256>>>();
    vout_copy_kernel<<<12288, 256>>>(v, out + (size_t)T_ * BCD);

    // One-time tf32 pre-conversion (inputs + weights)
    const int n4in = T_ * BCD / 4;
    cvt_tf32_kernel<<<(n4in + 255) / 256, 256>>>((const float4*)q, (float4*)cq, n4in);
    cvt_tf32_kernel<<<(n4in + 255) / 256, 256>>>((const float4*)k, (float4*)ck, n4in);
    cvt_tf32_kernel<<<(n4in + 255) / 256, 256>>>((const float4*)v, (float4*)cv, n4in);
    const int n4w = D_ * D_ / 4;
    cvt_tf32_kernel<<<(n4w + 255) / 256, 256>>>((const float4*)qw, (float4*)(wc + 0 * D_ * D_), n4w);
    cvt_tf32_kernel<<<(n4w + 255) / 256, 256>>>((const float4*)kw, (float4*)(wc + 1 * D_ * D_), n4w);
    cvt_tf32_kernel<<<(n4w + 255) / 256, 256>>>((const float4*)vw, (float4*)(wc + 2 * D_ * D_), n4w);
    cvt_tf32_kernel<<<(n4w + 255) / 256, 256>>>((const float4*)pw, (float4*)(wc + 3 * D_ * D_), n4w);

    for (int t = 0; t < T_; t++) {
        const float* qt = cq + (size_t)t * BCD;
        const float* kt = ck + (size_t)t * BCD;
        const float* vt = cv + (size_t)t * BCD;

        dense_mma_gemm<<<dim3(6, 32, 3), 256, DSM_BYTES>>>(
            qt, kt, vt, wc + 0 * D_ * D_, wc + 1 * D_ * D_, wc + 2 * D_ * D_,
            qb, kb, vb, 1);
        attn_mma_kernel<<<dim3(4, 96), 256>>>();
        dense_mma_gemm<<<dim3(6, 32, 1), 256, DSM_BYTES>>>(
            nullptr, nullptr, nullptr, wc + 3 * D_ * D_, nullptr, nullptr,
            pb, nullptr, nullptr, 0);
        bn_sum1_kernel<<<dim3(6, 8), 256>>>();
        bn_mean_kernel<<<3, 256>>>();
        bn_var1_kernel<<<dim3(6, 8), 256>>>();
        bn_var2_kernel<<<3, 256>>>();
        bn_apply_lif_kernel<<<12288, 256>>>(bnw, bnb, out + (size_t)t * BCD);
    }
}

// round 7
// speedup vs baseline: 2.9171x; 1.1042x over previous
#include <cuda_runtime.h>

typedef unsigned long long u64;
typedef unsigned int u32;

// Problem constants
#define T_  4
#define B_  8
#define C_  512
#define D_  768
#define H_  12
#define DH  64
#define BC  (B_*C_)          // 4096
#define BCD (BC*D_)          // 3145728

// Persistent scratch (allocation-free: __device__ globals)
__device__ float  g_mem[5][BCD];      // memq, memk, memv, mematt, mproj
__device__ float  g_spk2[BCD];        // sv (binary floats)
__device__ float  g_spk3[BCD];        // satt (binary floats)
__device__ float  g_x2[BCD];          // projection output (pre-BN)
__device__ u64    g_qb[BC * H_];      // packed Q spikes
__device__ u64    g_kb[BC * H_];      // packed K spikes
__device__ float  g_cq[T_ * BCD];     // tf32-preconverted inputs
__device__ float  g_ck[T_ * BCD];
__device__ float  g_cv[T_ * BCD];
__device__ float  g_wc[4][D_ * D_];   // tf32-preconverted weights qw,kw,vw,pw
__device__ double g_bnsum[32 * D_];   // per-m-tile fp64 partial sums
__device__ double g_bnsq[32 * D_];    // per-m-tile fp64 partial sum-of-squares
__device__ float  g_mean[D_];
__device__ float  g_rstd[D_];

// ---------------------------------------------------------------------------
__device__ __forceinline__ float tf32r(float x) {
    unsigned u;
    asm("cvt.rna.tf32.f32 %0, %1;" : "=r"(u) : "f"(x));
    return __uint_as_float(u);
}
__device__ __forceinline__ u32 smem_u32(const void* p) {
    u32 a;
    asm("{ .reg .u64 t; cvta.to.shared.u64 t, %1; cvt.u32.u64 %0, t; }" : "=r"(a) : "l"(p));
    return a;
}
// cp.async (plain sm_80 PTX)
#define CP_ASYNC16(saddr, gptr) \
    asm volatile("cp.async.ca.shared.global [%0], [%1], 16;" :: "r"(saddr), "l"(gptr))
#define CP_COMMIT() asm volatile("cp.async.commit_group;" ::: "memory")
#define CP_WAIT(n)  asm volatile("cp.async.wait_group %0;" :: "n"(n) : "memory")

// mma.sync m16n8k8 tf32 (fallback HMMA; proven rel_err=0.0)
__device__ __forceinline__ void mma_tf32(float* d, const u32* a, const u32* b) {
    asm volatile(
        "mma.sync.aligned.m16n8k8.row.col.f32.tf32.tf32.f32 "
        "{%0,%1,%2,%3}, {%4,%5,%6,%7}, {%8,%9}, {%0,%1,%2,%3};"
        : "+f"(d[0]), "+f"(d[1]), "+f"(d[2]), "+f"(d[3])
        : "r"(a[0]), "r"(a[1]), "r"(a[2]), "r"(a[3]), "r"(b[0]), "r"(b[1]));
}

// ---------------------------------------------------------------------------
__global__ void zero_mem_kernel() {
    // 5*BCD floats = 3,932,160 float4; grid sized exactly
    size_t i = (size_t)blockIdx.x * blockDim.x + threadIdx.x;
    ((float4*)&g_mem[0][0])[i] = make_float4(0.f, 0.f, 0.f, 0.f);
}

__global__ void vout_copy_kernel(const float* __restrict__ v, float* __restrict__ o) {
    const size_t n4 = (size_t)T_ * BCD / 4;
    size_t i = (size_t)blockIdx.x * blockDim.x + threadIdx.x;
    if (i < n4) {
        float4 val = ((const float4*)v)[i];
        float4* o4 = (float4*)o;
        o4[i]          = val;
        o4[i + n4]     = val;
        o4[i + 2 * n4] = val;
        o4[i + 3 * n4] = val;
    }
}

__global__ void cvt_tf32_kernel(const float4* __restrict__ src, float4* __restrict__ dst,
                                int n4) {
    int i = blockIdx.x * blockDim.x + threadIdx.x;
    if (i < n4) {
        float4 v = src[i];
        dst[i] = make_float4(tf32r(v.x), tf32r(v.y), tf32r(v.z), tf32r(v.w));
    }
}

// ---------------------------------------------------------------------------
// Dense TF32 GEMM on tensor cores, 3-stage cp.async, 1 barrier/chunk.
// CTA tile 128x128, BK=32, 8 warps 2(m)x4(n), warp tile 64x32.
// smem: 3 stages x (As[128][36] + Bs[128][36]) = 110592 B.
#define STAGE_BYTES 36864
#define DSM_BYTES   (3 * STAGE_BYTES)

__global__ __launch_bounds__(256, 2) void dense_mma_gemm(
    const float* __restrict__ Xq, const float* __restrict__ Xk, const float* __restrict__ Xv,
    const float* __restrict__ Wq, const float* __restrict__ Wk, const float* __restrict__ Wv,
    const float* __restrict__ bq, const float* __restrict__ bk, const float* __restrict__ bv,
    int mode)
{
    extern __shared__ char dsm[];
    const u32 sb = smem_u32(dsm);

    const int z = blockIdx.z;
    const float* X;
    const float* W;
    const float* bias;
    float* mem = nullptr;
    float* spk = nullptr;
    float* out = nullptr;
    u32*   bitout = nullptr;
    if (mode) {
        X    = (z == 0) ? Xq : ((z == 1) ? Xk : Xv);
        W    = (z == 0) ? Wq : ((z == 1) ? Wk : Wv);
        bias = (z == 0) ? bq : ((z == 1) ? bk : bv);
        mem  = g_mem[z];
        if (z == 2) spk = g_spk2;
        else bitout = (z == 0) ? (u32*)g_qb : (u32*)g_kb;
    } else {
        X = g_spk3; W = Wq; bias = bq; out = g_x2;
    }

    const int tid  = threadIdx.x;
    const int wid  = tid >> 5, lane = tid & 31;
    const int g    = lane >> 2, c = lane & 3;
    const int wm   = wid & 1;
    const int wn   = wid >> 1;
    const int m0   = blockIdx.y * 128;
    const int n0   = blockIdx.x * 128;

    float acc[4][4][4];
#pragma unroll
    for (int im = 0; im < 4; im++)
#pragma unroll
        for (int in = 0; in < 4; in++)
#pragma unroll
            for (int r = 0; r < 4; r++) acc[im][in][r] = 0.0f;

    const int row = tid >> 3, seg = tid & 7;

    auto issue_stage = [&](int buf, int chunk) {
        const int k0 = chunk * 32;
        const u32 sA = sb + buf * STAGE_BYTES;
        const u32 sB = sA + 18432;
#pragma unroll
        for (int pass = 0; pass < 4; pass++) {
            int rr = row + pass * 32;
            u32 off = (u32)((rr * 36 + seg * 4) * 4);
            CP_ASYNC16(sA + off, &X[(size_t)(m0 + rr) * 768 + k0 + seg * 4]);
            CP_ASYNC16(sB + off, &W[(size_t)(n0 + rr) * 768 + k0 + seg * 4]);
        }
    };

    issue_stage(0, 0); CP_COMMIT();
    issue_stage(1, 1); CP_COMMIT();

    for (int chunk = 0; chunk < 24; chunk++) {
        if (chunk == 23) { CP_WAIT(0); } else { CP_WAIT(1); }
        __syncthreads();

        const int buf = chunk % 3;
        const u32* Asu = (const u32*)(dsm + buf * STAGE_BYTES);
        const u32* Bsu = (const u32*)(dsm + buf * STAGE_BYTES + 18432);
#pragma unroll
        for (int ka = 0; ka < 4; ka++) {
            const int kk = ka * 8;
            u32 a[4][4], b[4][2];
#pragma unroll
            for (int im = 0; im < 4; im++) {
                int r = wm * 64 + im * 16 + g;
                a[im][0] = Asu[r * 36 + kk + c];
                a[im][1] = Asu[(r + 8) * 36 + kk + c];
                a[im][2] = Asu[r * 36 + kk + c + 4];
                a[im][3] = Asu[(r + 8) * 36 + kk + c + 4];
            }
#pragma unroll
            for (int in = 0; in < 4; in++) {
                int nn = wn * 32 + in * 8 + g;
                b[in][0] = Bsu[nn * 36 + kk + c];
                b[in][1] = Bsu[nn * 36 + kk + c + 4];
            }
#pragma unroll
            for (int im = 0; im < 4; im++)
#pragma unroll
                for (int in = 0; in < 4; in++)
                    mma_tf32(acc[im][in], a[im], b[in]);
        }
        if (chunk + 2 < 24) {
            issue_stage((chunk + 2) % 3, chunk + 2);
            CP_COMMIT();
        }
    }

    // Epilogue: stage 64-row halves in smem, coalesced bias+LIF/store.
    // mode==0 additionally accumulates per-column fp64 BN partials.
    float* sE = (float*)dsm;              // [64][132] floats (buffer 0 region)
    double* dred = (double*)(dsm + 2 * STAGE_BYTES);  // 512 doubles (stage-2 region)
    double ds = 0.0, dss = 0.0;
    const int nc = wid & 3;
    const int rh = wid >> 2;
    const int nn = n0 + nc * 32 + lane;
    const float bvv = bias[nn];
    const int head = nn >> 6, half = (nn >> 5) & 1;

#pragma unroll
    for (int p = 0; p < 2; p++) {
        __syncthreads();
        if (wm == p) {
#pragma unroll
            for (int im = 0; im < 4; im++)
#pragma unroll
                for (int in = 0; in < 4; in++) {
                    int rr   = im * 16 + g;
                    int colb = wn * 32 + in * 8 + 2 * c;
                    sE[rr * 132 + colb]           = acc[im][in][0];
                    sE[rr * 132 + colb + 1]       = acc[im][in][1];
                    sE[(rr + 8) * 132 + colb]     = acc[im][in][2];
                    sE[(rr + 8) * 132 + colb + 1] = acc[im][in][3];
                }
        }
        __syncthreads();
        for (int rr = rh * 32; rr < rh * 32 + 32; rr++) {
            float y = sE[rr * 132 + nc * 32 + lane] + bvv;
            int m = m0 + p * 64 + rr;
            size_t idx = (size_t)m * 768 + nn;
            if (mode) {
                float mp    = mem[idx];
                float reset = (mp > 1.0f) ? 1.0f : 0.0f;
                float mn    = 0.6f * mp + y - reset;
                mem[idx] = mn;
                float sp = (mn > 1.0f) ? 1.0f : 0.0f;
                if (z == 2) {
                    spk[idx] = sp;
                } else {
                    u32 bits = __ballot_sync(0xffffffffu, sp > 0.5f);
                    if (lane == 0) bitout[(m * H_ + head) * 2 + half] = bits;
                }
            } else {
                out[idx] = y;
                ds  += (double)y;
                dss += (double)y * (double)y;
            }
        }
    }

    if (mode == 0) {
        const int ci = nc * 32 + lane;           // column within tile (0..127)
        dred[rh * 128 + ci]       = ds;
        dred[256 + rh * 128 + ci] = dss;
        __syncthreads();
        if (rh == 0) {
            double s  = dred[ci] + dred[128 + ci];
            double qq = dred[256 + ci] + dred[384 + ci];
            g_bnsum[blockIdx.y * 768 + nn] = s;
            g_bnsq[blockIdx.y * 768 + nn]  = qq;
        }
    }
}

// ---------------------------------------------------------------------------
// Fused attention on tensor cores (proven R6): inline popcount S-frags + HMMA PV.
__global__ __launch_bounds__(256) void attn_mma_kernel() {
    __shared__ u64   Kb[512];
    __shared__ float Vs[64 * 36];

    const int bh = blockIdx.y;
    const int b  = bh / H_;
    const int h  = bh - b * H_;
    const int i0 = blockIdx.x * 128;
    const int tid = threadIdx.x;
    const int wid = tid >> 5, lane = tid & 31;
    const int g = lane >> 2, cc = lane & 3;

    Kb[tid]       = g_kb[(size_t)(b * C_ + tid) * H_ + h];
    Kb[tid + 256] = g_kb[(size_t)(b * C_ + tid + 256) * H_ + h];

    const int irow0 = i0 + wid * 16 + g;
    const u64 q0 = g_qb[(size_t)(b * C_ + irow0) * H_ + h];
    const u64 q1 = g_qb[(size_t)(b * C_ + irow0 + 8) * H_ + h];

    const float* V = g_spk2 + (size_t)b * C_ * D_ + h * DH;

    float acc[8][4];
#pragma unroll
    for (int in = 0; in < 8; in++)
#pragma unroll
        for (int r = 0; r < 4; r++) acc[in][r] = 0.0f;

    const int vj = tid >> 3, vd = tid & 7;
    float4 va = *(const float4*)&V[(size_t)vj * 768 + vd * 4];
    float4 vb = *(const float4*)&V[(size_t)vj * 768 + 32 + vd * 4];
    __syncthreads();

    const u32* Vsu = (const u32*)Vs;
    for (int c = 0; c < 16; c++) {
        Vs[(4 * vd + 0) * 36 + vj] = va.x;
        Vs[(4 * vd + 1) * 36 + vj] = va.y;
        Vs[(4 * vd + 2) * 36 + vj] = va.z;
        Vs[(4 * vd + 3) * 36 + vj] = va.w;
        Vs[(32 + 4 * vd + 0) * 36 + vj] = vb.x;
        Vs[(32 + 4 * vd + 1) * 36 + vj] = vb.y;
        Vs[(32 + 4 * vd + 2) * 36 + vj] = vb.z;
        Vs[(32 + 4 * vd + 3) * 36 + vj] = vb.w;
        __syncthreads();
        if (c < 15) {
            va = *(const float4*)&V[(size_t)((c + 1) * 32 + vj) * 768 + vd * 4];
            vb = *(const float4*)&V[(size_t)((c + 1) * 32 + vj) * 768 + 32 + vd * 4];
        }

#pragma unroll
        for (int ka = 0; ka < 4; ka++) {
            const int jb = c * 32 + ka * 8;
            const u64 kb0 = Kb[jb + cc];
            const u64 kb4 = Kb[jb + cc + 4];
            u32 a[4];
            a[0] = __float_as_uint(tf32r(0.18f * (float)__popcll(q0 & kb0)));
            a[1] = __float_as_uint(tf32r(0.18f * (float)__popcll(q1 & kb0)));
            a[2] = __float_as_uint(tf32r(0.18f * (float)__popcll(q0 & kb4)));
            a[3] = __float_as_uint(tf32r(0.18f * (float)__popcll(q1 & kb4)));
#pragma unroll
            for (int in = 0; in < 8; in++) {
                u32 bfr[2];
                bfr[0] = Vsu[(in * 8 + g) * 36 + ka * 8 + cc];
                bfr[1] = Vsu[(in * 8 + g) * 36 + ka * 8 + cc + 4];
                mma_tf32(acc[in], a, bfr);
            }
        }
        __syncthreads();
    }

    float* mem = g_mem[3];
    float* spk = g_spk3;
#pragma unroll
    for (int in = 0; in < 8; in++) {
        int col = h * DH + in * 8 + 2 * cc;
        size_t idx0 = (size_t)(b * C_ + irow0) * 768 + col;
        size_t idx1 = (size_t)(b * C_ + irow0 + 8) * 768 + col;
#pragma unroll
        for (int e = 0; e < 2; e++) {
            float mp    = mem[idx0 + e];
            float reset = (mp > 1.0f) ? 1.0f : 0.0f;
            float mn    = 0.6f * mp + acc[in][e] - reset;
            mem[idx0 + e] = mn;
            spk[idx0 + e] = (mn > 1.0f) ? 1.0f : 0.0f;
            float mp1    = mem[idx1 + e];
            float reset1 = (mp1 > 1.0f) ? 1.0f : 0.0f;
            float mn1    = 0.6f * mp1 + acc[in][2 + e] - reset1;
            mem[idx1 + e] = mn1;
            spk[idx1 + e] = (mn1 > 1.0f) ? 1.0f : 0.0f;
        }
    }
}

// ---------------------------------------------------------------------------
// BN finalize: combine 32 fp64 partials -> mean, rstd (single-pass var in fp64).
__global__ void bn_finalize_kernel() {
    int ch = blockIdx.x * blockDim.x + threadIdx.x;
    if (ch < 768) {
        double s = 0.0, q = 0.0;
#pragma unroll
        for (int p = 0; p < 32; p++) {
            s += g_bnsum[p * 768 + ch];
            q += g_bnsq[p * 768 + ch];
        }
        double mean = s * (1.0 / 4096.0);
        double var  = q * (1.0 / 4096.0) - mean * mean;
        g_mean[ch] = (float)mean;
        g_rstd[ch] = rsqrtf((float)var + 1e-5f);
    }
}

// BN apply + final LIF -> output att[t], float4-vectorized (768 % 4 == 0).
__global__ void bn_apply_lif_kernel(const float* __restrict__ bnw,
                                    const float* __restrict__ bnb,
                                    float* __restrict__ outp) {
    size_t i4 = (size_t)blockIdx.x * blockDim.x + threadIdx.x;  // grid = BCD/4
    size_t base = i4 * 4;
    int ch = (int)(base % 768);
    float4 x  = ((const float4*)g_x2)[i4];
    float4 mp = ((const float4*)g_mem[4])[i4];
    float xs[4] = {x.x, x.y, x.z, x.w};
    float ms[4] = {mp.x, mp.y, mp.z, mp.w};
    float4 mo, oo;
    float* mop = (float*)&mo;
    float* oop = (float*)&oo;
#pragma unroll
    for (int j = 0; j < 4; j++) {
        int cj = ch + j;
        float cur = (xs[j] - g_mean[cj]) * g_rstd[cj] * bnw[cj] + bnb[cj];
        float reset = (ms[j] > 1.0f) ? 1.0f : 0.0f;
        float mn    = 0.6f * ms[j] + cur - reset;
        mop[j] = mn;
        oop[j] = (mn > 1.0f) ? 1.0f : 0.0f;
    }
    ((float4*)g_mem[4])[i4] = mo;
    ((float4*)outp)[i4] = oo;
}

// ---------------------------------------------------------------------------
extern "C" void kernel_launch(void* const* d_in, const int* in_sizes, int n_in,
                              void* d_out, int out_size) {
    (void)in_sizes; (void)n_in; (void)out_size;
    const float* q   = (const float*)d_in[0];
    const float* k   = (const float*)d_in[1];
    const float* v   = (const float*)d_in[2];
    const float* qw  = (const float*)d_in[3];
    const float* qb  = (const float*)d_in[4];
    const float* kw  = (const float*)d_in[5];
    const float* kb  = (const float*)d_in[6];
    const float* vw  = (const float*)d_in[7];
    const float* vb  = (const float*)d_in[8];
    const float* pw  = (const float*)d_in[9];
    const float* pb  = (const float*)d_in[10];
    const float* bnw = (const float*)d_in[11];
    const float* bnb = (const float*)d_in[12];
    float* out = (float*)d_out;

    cudaFuncSetAttribute(dense_mma_gemm, cudaFuncAttributeMaxDynamicSharedMemorySize,
                         DSM_BYTES);

    float* cq; cudaGetSymbolAddress((void**)&cq, g_cq);
    float* ck; cudaGetSymbolAddress((void**)&ck, g_ck);
    float* cv; cudaGetSymbolAddress((void**)&cv, g_cv);
    float* wc; cudaGetSymbolAddress((void**)&wc, g_wc);

    zero_mem_kernel<<<15360, 256>>>();
    vout_copy_kernel<<<12288, 256>>>(v, out + (size_t)T_ * BCD);

    const int n4in = T_ * BCD / 4;
    cvt_tf32_kernel<<<(n4in + 255) / 256, 256>>>((const float4*)q, (float4*)cq, n4in);
    cvt_tf32_kernel<<<(n4in + 255) / 256, 256>>>((const float4*)k, (float4*)ck, n4in);
    cvt_tf32_kernel<<<(n4in + 255) / 256, 256>>>((const float4*)v, (float4*)cv, n4in);
    const int n4w = D_ * D_ / 4;
    cvt_tf32_kernel<<<(n4w + 255) / 256, 256>>>((const float4*)qw, (float4*)(wc + 0 * D_ * D_), n4w);
    cvt_tf32_kernel<<<(n4w + 255) / 256, 256>>>((const float4*)kw, (float4*)(wc + 1 * D_ * D_), n4w);
    cvt_tf32_kernel<<<(n4w + 255) / 256, 256>>>((const float4*)vw, (float4*)(wc + 2 * D_ * D_), n4w);
    cvt_tf32_kernel<<<(n4w + 255) / 256, 256>>>((const float4*)pw, (float4*)(wc + 3 * D_ * D_), n4w);

    for (int t = 0; t < T_; t++) {
        const float* qt = cq + (size_t)t * BCD;
        const float* kt = ck + (size_t)t * BCD;
        const float* vt = cv + (size_t)t * BCD;

        dense_mma_gemm<<<dim3(6, 32, 3), 256, DSM_BYTES>>>(
            qt, kt, vt, wc + 0 * D_ * D_, wc + 1 * D_ * D_, wc + 2 * D_ * D_,
            qb, kb, vb, 1);
        attn_mma_kernel<<<dim3(4, 96), 256>>>();
        dense_mma_gemm<<<dim3(6, 32, 1), 256, DSM_BYTES>>>(
            nullptr, nullptr, nullptr, wc + 3 * D_ * D_, nullptr, nullptr,
            pb, nullptr, nullptr, 0);
        bn_finalize_kernel<<<3, 256>>>();
        bn_apply_lif_kernel<<<3072, 256>>>(bnw, bnb, out + (size_t)t * BCD);
    }
}

// round 8
// speedup vs baseline: 3.1492x; 1.0796x over previous
#include <cuda_runtime.h>

typedef unsigned long long u64;
typedef unsigned int u32;

// Problem constants
#define T_  4
#define B_  8
#define C_  512
#define D_  768
#define H_  12
#define DH  64
#define BC  (B_*C_)          // 4096
#define BCD (BC*D_)          // 3145728

// Persistent scratch (allocation-free: __device__ globals)
__device__ float  g_mem[5][BCD];
__device__ float  g_spk2[BCD];        // sv
__device__ float  g_spk3[BCD];        // satt
__device__ float  g_x2[BCD];          // projection output (pre-BN)
__device__ u64    g_qb[BC * H_];
__device__ u64    g_kb[BC * H_];
__device__ float  g_cq[T_ * BCD];
__device__ float  g_ck[T_ * BCD];
__device__ float  g_cv[T_ * BCD];
__device__ float  g_wc[4][D_ * D_];
__device__ double g_bnsum[32 * D_];
__device__ double g_bnsq[32 * D_];
__device__ float  g_mean[D_];
__device__ float  g_rstd[D_];

// ---------------------------------------------------------------------------
__device__ __forceinline__ float tf32r(float x) {
    unsigned u;
    asm("cvt.rna.tf32.f32 %0, %1;" : "=r"(u) : "f"(x));
    return __uint_as_float(u);
}
__device__ __forceinline__ u32 smem_u32(const void* p) {
    u32 a;
    asm("{ .reg .u64 t; cvta.to.shared.u64 t, %1; cvt.u32.u64 %0, t; }" : "=r"(a) : "l"(p));
    return a;
}
#define CP_ASYNC16(saddr, gptr) \
    asm volatile("cp.async.ca.shared.global [%0], [%1], 16;" :: "r"(saddr), "l"(gptr))
#define CP_COMMIT() asm volatile("cp.async.commit_group;" ::: "memory")
#define CP_WAIT(n)  asm volatile("cp.async.wait_group %0;" :: "n"(n) : "memory")

__device__ __forceinline__ void mma_tf32(float* d, const u32* a, const u32* b) {
    asm volatile(
        "mma.sync.aligned.m16n8k8.row.col.f32.tf32.tf32.f32 "
        "{%0,%1,%2,%3}, {%4,%5,%6,%7}, {%8,%9}, {%0,%1,%2,%3};"
        : "+f"(d[0]), "+f"(d[1]), "+f"(d[2]), "+f"(d[3])
        : "r"(a[0]), "r"(a[1]), "r"(a[2]), "r"(a[3]), "r"(b[0]), "r"(b[1]));
}
// ldmatrix x4: 4 8x8(b16) tiles == 4 8x4(b32) tiles; lane group 8i provides tile i rows.
__device__ __forceinline__ void ldsm_x4(u32* r, u32 saddr) {
    asm volatile("ldmatrix.sync.aligned.m8n8.x4.shared.b16 {%0,%1,%2,%3}, [%4];"
                 : "=r"(r[0]), "=r"(r[1]), "=r"(r[2]), "=r"(r[3]) : "r"(saddr));
}

// ---------------------------------------------------------------------------
__global__ void zero_mem_kernel() {
    size_t i = (size_t)blockIdx.x * blockDim.x + threadIdx.x;  // grid exact: 5*BCD/4
    ((float4*)&g_mem[0][0])[i] = make_float4(0.f, 0.f, 0.f, 0.f);
}

__global__ void vout_copy_kernel(const float* __restrict__ v, float* __restrict__ o) {
    const size_t n4 = (size_t)T_ * BCD / 4;
    size_t i = (size_t)blockIdx.x * blockDim.x + threadIdx.x;
    if (i < n4) {
        float4 val = ((const float4*)v)[i];
        float4* o4 = (float4*)o;
        o4[i]          = val;
        o4[i + n4]     = val;
        o4[i + 2 * n4] = val;
        o4[i + 3 * n4] = val;
    }
}

// Single merged TF32 pre-conversion: q,k,v (T_*BCD each) + 4 weights (D_*D_ each).
#define N4_IN  (T_ * BCD / 4)          // 3145728 float4 per input
#define N4_W   (D_ * D_ / 4)           // 147456 float4 per weight
__global__ void cvt_all_kernel(const float4* __restrict__ q, const float4* __restrict__ k,
                               const float4* __restrict__ v, const float4* __restrict__ qw,
                               const float4* __restrict__ kw, const float4* __restrict__ vw,
                               const float4* __restrict__ pw) {
    size_t i = (size_t)blockIdx.x * blockDim.x + threadIdx.x;
    const float4* src;
    float4* dst;
    if (i < 3 * (size_t)N4_IN) {
        int which = (int)(i / N4_IN);
        size_t off = i - (size_t)which * N4_IN;
        src = (which == 0 ? q : (which == 1 ? k : v)) + off;
        dst = (float4*)(which == 0 ? g_cq : (which == 1 ? g_ck : g_cv)) + off;
    } else {
        size_t j = i - 3 * (size_t)N4_IN;
        if (j >= 4 * (size_t)N4_W) return;
        int which = (int)(j / N4_W);
        size_t off = j - (size_t)which * N4_W;
        src = (which == 0 ? qw : (which == 1 ? kw : (which == 2 ? vw : pw))) + off;
        dst = (float4*)&g_wc[which][0] + off;
    }
    float4 x = *src;
    *dst = make_float4(tf32r(x.x), tf32r(x.y), tf32r(x.z), tf32r(x.w));
}

// ---------------------------------------------------------------------------
// Dense TF32 GEMM, 3-stage cp.async + ldmatrix fragment loads.
#define STAGE_BYTES 36864
#define DSM_BYTES   (3 * STAGE_BYTES)

__global__ __launch_bounds__(256, 2) void dense_mma_gemm(
    const float* __restrict__ Xq, const float* __restrict__ Xk, const float* __restrict__ Xv,
    const float* __restrict__ Wq, const float* __restrict__ Wk, const float* __restrict__ Wv,
    const float* __restrict__ bq, const float* __restrict__ bk, const float* __restrict__ bv,
    int mode)
{
    extern __shared__ char dsm[];
    const u32 sb = smem_u32(dsm);

    const int z = blockIdx.z;
    const float* X;
    const float* W;
    const float* bias;
    float* mem = nullptr;
    float* spk = nullptr;
    float* out = nullptr;
    u32*   bitout = nullptr;
    if (mode) {
        X    = (z == 0) ? Xq : ((z == 1) ? Xk : Xv);
        W    = (z == 0) ? Wq : ((z == 1) ? Wk : Wv);
        bias = (z == 0) ? bq : ((z == 1) ? bk : bv);
        mem  = g_mem[z];
        if (z == 2) spk = g_spk2;
        else bitout = (z == 0) ? (u32*)g_qb : (u32*)g_kb;
    } else {
        X = g_spk3; W = Wq; bias = bq; out = g_x2;
    }

    const int tid  = threadIdx.x;
    const int wid  = tid >> 5, lane = tid & 31;
    const int g    = lane >> 2, c = lane & 3;
    const int wm   = wid & 1;
    const int wn   = wid >> 1;
    const int m0   = blockIdx.y * 128;
    const int n0   = blockIdx.x * 128;

    float acc[4][4][4];
#pragma unroll
    for (int im = 0; im < 4; im++)
#pragma unroll
        for (int in = 0; in < 4; in++)
#pragma unroll
            for (int r = 0; r < 4; r++) acc[im][in][r] = 0.0f;

    const int row = tid >> 3, seg = tid & 7;

    auto issue_stage = [&](int buf, int chunk) {
        const int k0 = chunk * 32;
        const u32 sA = sb + buf * STAGE_BYTES;
        const u32 sB = sA + 18432;
#pragma unroll
        for (int pass = 0; pass < 4; pass++) {
            int rr = row + pass * 32;
            u32 off = (u32)((rr * 36 + seg * 4) * 4);
            CP_ASYNC16(sA + off, &X[(size_t)(m0 + rr) * 768 + k0 + seg * 4]);
            CP_ASYNC16(sB + off, &W[(size_t)(n0 + rr) * 768 + k0 + seg * 4]);
        }
    };

    // ldmatrix per-thread base offsets (bytes within a stage)
    const int li = lane & 7, bi = lane >> 3;
    // A fragment (16x8): tile bi -> row += (bi&1)*8, col += (bi>>1)*4
    const u32 aOff = (u32)(((wm * 64 + li + ((bi & 1) << 3)) * 36 + ((bi >> 1) << 2)) * 4);
    // B fragments (two n-blocks of 8 per x4): tile bi -> row += (bi>>1)*8, col += (bi&1)*4
    const u32 bOff = (u32)(18432 + ((wn * 32 + ((bi >> 1) << 3) + li) * 36 + ((bi & 1) << 2)) * 4);

    issue_stage(0, 0); CP_COMMIT();
    issue_stage(1, 1); CP_COMMIT();

    for (int chunk = 0; chunk < 24; chunk++) {
        if (chunk == 23) { CP_WAIT(0); } else { CP_WAIT(1); }
        __syncthreads();

        const u32 stBase = sb + (chunk % 3) * STAGE_BYTES;
#pragma unroll
        for (int ka = 0; ka < 4; ka++) {
            u32 a[4][4], b[4][2];
#pragma unroll
            for (int im = 0; im < 4; im++)
                ldsm_x4(a[im], stBase + aOff + (u32)((im * 16 * 36 + ka * 8) * 4));
#pragma unroll
            for (int ip = 0; ip < 2; ip++) {
                u32 t4[4];
                ldsm_x4(t4, stBase + bOff + (u32)((ip * 16 * 36 + ka * 8) * 4));
                b[2 * ip][0]     = t4[0];
                b[2 * ip][1]     = t4[1];
                b[2 * ip + 1][0] = t4[2];
                b[2 * ip + 1][1] = t4[3];
            }
#pragma unroll
            for (int im = 0; im < 4; im++)
#pragma unroll
                for (int in = 0; in < 4; in++)
                    mma_tf32(acc[im][in], a[im], b[in]);
        }
        if (chunk + 2 < 24) {
            issue_stage((chunk + 2) % 3, chunk + 2);
            CP_COMMIT();
        }
    }

    // Epilogue (+ fused BN partials for mode==0)
    float* sE = (float*)dsm;
    double* dred = (double*)(dsm + 2 * STAGE_BYTES);
    double ds = 0.0, dss = 0.0;
    const int nc = wid & 3;
    const int rh = wid >> 2;
    const int nn = n0 + nc * 32 + lane;
    const float bvv = bias[nn];
    const int head = nn >> 6, half = (nn >> 5) & 1;

#pragma unroll
    for (int p = 0; p < 2; p++) {
        __syncthreads();
        if (wm == p) {
#pragma unroll
            for (int im = 0; im < 4; im++)
#pragma unroll
                for (int in = 0; in < 4; in++) {
                    int rr   = im * 16 + g;
                    int colb = wn * 32 + in * 8 + 2 * c;
                    sE[rr * 132 + colb]           = acc[im][in][0];
                    sE[rr * 132 + colb + 1]       = acc[im][in][1];
                    sE[(rr + 8) * 132 + colb]     = acc[im][in][2];
                    sE[(rr + 8) * 132 + colb + 1] = acc[im][in][3];
                }
        }
        __syncthreads();
        for (int rr = rh * 32; rr < rh * 32 + 32; rr++) {
            float y = sE[rr * 132 + nc * 32 + lane] + bvv;
            int m = m0 + p * 64 + rr;
            size_t idx = (size_t)m * 768 + nn;
            if (mode) {
                float mp    = mem[idx];
                float reset = (mp > 1.0f) ? 1.0f : 0.0f;
                float mn    = 0.6f * mp + y - reset;
                mem[idx] = mn;
                float sp = (mn > 1.0f) ? 1.0f : 0.0f;
                if (z == 2) {
                    spk[idx] = sp;
                } else {
                    u32 bits = __ballot_sync(0xffffffffu, sp > 0.5f);
                    if (lane == 0) bitout[(m * H_ + head) * 2 + half] = bits;
                }
            } else {
                out[idx] = y;
                ds  += (double)y;
                dss += (double)y * (double)y;
            }
        }
    }

    if (mode == 0) {
        const int ci = nc * 32 + lane;
        dred[rh * 128 + ci]       = ds;
        dred[256 + rh * 128 + ci] = dss;
        __syncthreads();
        if (rh == 0) {
            g_bnsum[blockIdx.y * 768 + nn] = dred[ci] + dred[128 + ci];
            g_bnsq[blockIdx.y * 768 + nn]  = dred[256 + ci] + dred[384 + ci];
        }
    }
}

// ---------------------------------------------------------------------------
// Fused attention (proven): inline popcount S-frags + HMMA PV + LIF.
__global__ __launch_bounds__(256) void attn_mma_kernel() {
    __shared__ u64   Kb[512];
    __shared__ float Vs[64 * 36];

    const int bh = blockIdx.y;
    const int b  = bh / H_;
    const int h  = bh - b * H_;
    const int i0 = blockIdx.x * 128;
    const int tid = threadIdx.x;
    const int wid = tid >> 5, lane = tid & 31;
    const int g = lane >> 2, cc = lane & 3;

    Kb[tid]       = g_kb[(size_t)(b * C_ + tid) * H_ + h];
    Kb[tid + 256] = g_kb[(size_t)(b * C_ + tid + 256) * H_ + h];

    const int irow0 = i0 + wid * 16 + g;
    const u64 q0 = g_qb[(size_t)(b * C_ + irow0) * H_ + h];
    const u64 q1 = g_qb[(size_t)(b * C_ + irow0 + 8) * H_ + h];

    const float* V = g_spk2 + (size_t)b * C_ * D_ + h * DH;

    float acc[8][4];
#pragma unroll
    for (int in = 0; in < 8; in++)
#pragma unroll
        for (int r = 0; r < 4; r++) acc[in][r] = 0.0f;

    const int vj = tid >> 3, vd = tid & 7;
    float4 va = *(const float4*)&V[(size_t)vj * 768 + vd * 4];
    float4 vb = *(const float4*)&V[(size_t)vj * 768 + 32 + vd * 4];
    __syncthreads();

    const u32* Vsu = (const u32*)Vs;
    for (int c = 0; c < 16; c++) {
        Vs[(4 * vd + 0) * 36 + vj] = va.x;
        Vs[(4 * vd + 1) * 36 + vj] = va.y;
        Vs[(4 * vd + 2) * 36 + vj] = va.z;
        Vs[(4 * vd + 3) * 36 + vj] = va.w;
        Vs[(32 + 4 * vd + 0) * 36 + vj] = vb.x;
        Vs[(32 + 4 * vd + 1) * 36 + vj] = vb.y;
        Vs[(32 + 4 * vd + 2) * 36 + vj] = vb.z;
        Vs[(32 + 4 * vd + 3) * 36 + vj] = vb.w;
        __syncthreads();
        if (c < 15) {
            va = *(const float4*)&V[(size_t)((c + 1) * 32 + vj) * 768 + vd * 4];
            vb = *(const float4*)&V[(size_t)((c + 1) * 32 + vj) * 768 + 32 + vd * 4];
        }

#pragma unroll
        for (int ka = 0; ka < 4; ka++) {
            const int jb = c * 32 + ka * 8;
            const u64 kb0 = Kb[jb + cc];
            const u64 kb4 = Kb[jb + cc + 4];
            u32 a[4];
            a[0] = __float_as_uint(tf32r(0.18f * (float)__popcll(q0 & kb0)));
            a[1] = __float_as_uint(tf32r(0.18f * (float)__popcll(q1 & kb0)));
            a[2] = __float_as_uint(tf32r(0.18f * (float)__popcll(q0 & kb4)));
            a[3] = __float_as_uint(tf32r(0.18f * (float)__popcll(q1 & kb4)));
#pragma unroll
            for (int in = 0; in < 8; in++) {
                u32 bfr[2];
                bfr[0] = Vsu[(in * 8 + g) * 36 + ka * 8 + cc];
                bfr[1] = Vsu[(in * 8 + g) * 36 + ka * 8 + cc + 4];
                mma_tf32(acc[in], a, bfr);
            }
        }
        __syncthreads();
    }

    float* mem = g_mem[3];
    float* spk = g_spk3;
#pragma unroll
    for (int in = 0; in < 8; in++) {
        int col = h * DH + in * 8 + 2 * cc;
        size_t idx0 = (size_t)(b * C_ + irow0) * 768 + col;
        size_t idx1 = (size_t)(b * C_ + irow0 + 8) * 768 + col;
#pragma unroll
        for (int e = 0; e < 2; e++) {
            float mp    = mem[idx0 + e];
            float reset = (mp > 1.0f) ? 1.0f : 0.0f;
            float mn    = 0.6f * mp + acc[in][e] - reset;
            mem[idx0 + e] = mn;
            spk[idx0 + e] = (mn > 1.0f) ? 1.0f : 0.0f;
            float mp1    = mem[idx1 + e];
            float reset1 = (mp1 > 1.0f) ? 1.0f : 0.0f;
            float mn1    = 0.6f * mp1 + acc[in][2 + e] - reset1;
            mem[idx1 + e] = mn1;
            spk[idx1 + e] = (mn1 > 1.0f) ? 1.0f : 0.0f;
        }
    }
}

// ---------------------------------------------------------------------------
__global__ void bn_finalize_kernel() {
    int ch = blockIdx.x * blockDim.x + threadIdx.x;
    if (ch < 768) {
        double s = 0.0, q = 0.0;
#pragma unroll
        for (int p = 0; p < 32; p++) {
            s += g_bnsum[p * 768 + ch];
            q += g_bnsq[p * 768 + ch];
        }
        double mean = s * (1.0 / 4096.0);
        double var  = q * (1.0 / 4096.0) - mean * mean;
        g_mean[ch] = (float)mean;
        g_rstd[ch] = rsqrtf((float)var + 1e-5f);
    }
}

__global__ void bn_apply_lif_kernel(const float* __restrict__ bnw,
                                    const float* __restrict__ bnb,
                                    float* __restrict__ outp) {
    size_t i4 = (size_t)blockIdx.x * blockDim.x + threadIdx.x;
    size_t base = i4 * 4;
    int ch = (int)(base % 768);
    float4 x  = ((const float4*)g_x2)[i4];
    float4 mp = ((const float4*)g_mem[4])[i4];
    float xs[4] = {x.x, x.y, x.z, x.w};
    float ms[4] = {mp.x, mp.y, mp.z, mp.w};
    float4 mo, oo;
    float* mop = (float*)&mo;
    float* oop = (float*)&oo;
#pragma unroll
    for (int j = 0; j < 4; j++) {
        int cj = ch + j;
        float cur = (xs[j] - g_mean[cj]) * g_rstd[cj] * bnw[cj] + bnb[cj];
        float reset = (ms[j] > 1.0f) ? 1.0f : 0.0f;
        float mn    = 0.6f * ms[j] + cur - reset;
        mop[j] = mn;
        oop[j] = (mn > 1.0f) ? 1.0f : 0.0f;
    }
    ((float4*)g_mem[4])[i4] = mo;
    ((float4*)outp)[i4] = oo;
}

// ---------------------------------------------------------------------------
extern "C" void kernel_launch(void* const* d_in, const int* in_sizes, int n_in,
                              void* d_out, int out_size) {
    (void)in_sizes; (void)n_in; (void)out_size;
    const float* q   = (const float*)d_in[0];
    const float* k   = (const float*)d_in[1];
    const float* v   = (const float*)d_in[2];
    const float* qb  = (const float*)d_in[4];
    const float* kb  = (const float*)d_in[6];
    const float* vb  = (const float*)d_in[8];
    const float* pb  = (const float*)d_in[10];
    const float* bnw = (const float*)d_in[11];
    const float* bnb = (const float*)d_in[12];
    float* out = (float*)d_out;

    cudaFuncSetAttribute(dense_mma_gemm, cudaFuncAttributeMaxDynamicSharedMemorySize,
                         DSM_BYTES);

    float* cq; cudaGetSymbolAddress((void**)&cq, g_cq);
    float* ck; cudaGetSymbolAddress((void**)&ck, g_ck);
    float* cv; cudaGetSymbolAddress((void**)&cv, g_cv);
    float* wc; cudaGetSymbolAddress((void**)&wc, g_wc);

    // launch 1-3 (preamble), then step-1 GEMM = launch 4, attn = 5, proj = 6
    zero_mem_kernel<<<15360, 256>>>();
    vout_copy_kernel<<<12288, 256>>>(v, out + (size_t)T_ * BCD);
    const int totalCvt = 3 * N4_IN + 4 * N4_W;
    cvt_all_kernel<<<(totalCvt + 255) / 256, 256>>>(
        (const float4*)q, (const float4*)k, (const float4*)v,
        (const float4*)d_in[3], (const float4*)d_in[5],
        (const float4*)d_in[7], (const float4*)d_in[9]);

    for (int t = 0; t < T_; t++) {
        const float* qt = cq + (size_t)t * BCD;
        const float* kt = ck + (size_t)t * BCD;
        const float* vt = cv + (size_t)t * BCD;

        dense_mma_gemm<<<dim3(6, 32, 3), 256, DSM_BYTES>>>(
            qt, kt, vt, wc + 0 * D_ * D_, wc + 1 * D_ * D_, wc + 2 * D_ * D_,
            qb, kb, vb, 1);
        attn_mma_kernel<<<dim3(4, 96), 256>>>();
        dense_mma_gemm<<<dim3(6, 32, 1), 256, DSM_BYTES>>>(
            nullptr, nullptr, nullptr, wc + 3 * D_ * D_, nullptr, nullptr,
            pb, nullptr, nullptr, 0);
        bn_finalize_kernel<<<3, 256>>>();
        bn_apply_lif_kernel<<<3072, 256>>>(bnw, bnb, out + (size_t)t * BCD);
    }
}

// round 9
// speedup vs baseline: 3.4580x; 1.0981x over previous
#include <cuda_runtime.h>

typedef unsigned long long u64;
typedef unsigned int u32;

// Problem constants
#define T_  4
#define B_  8
#define C_  512
#define D_  768
#define H_  12
#define DH  64
#define BC  (B_*C_)          // 4096
#define BCD (BC*D_)          // 3145728

// Persistent scratch (allocation-free: __device__ globals)
__device__ float  g_mem[5][BCD];
__device__ float  g_spk2[BCD];        // sv
__device__ float  g_spk3[BCD];        // satt
__device__ float  g_x2[BCD];          // projection output (pre-BN)
__device__ u64    g_qb[BC * H_];
__device__ u64    g_kb[BC * H_];
__device__ float  g_cq[T_ * BCD];
__device__ float  g_ck[T_ * BCD];
__device__ float  g_cv[T_ * BCD];
__device__ float  g_wc[4][D_ * D_];
__device__ double g_bnsum[32 * D_];
__device__ double g_bnsq[32 * D_];
__device__ float  g_mean[D_];
__device__ float  g_rstd[D_];

// ---------------------------------------------------------------------------
__device__ __forceinline__ float tf32r(float x) {
    unsigned u;
    asm("cvt.rna.tf32.f32 %0, %1;" : "=r"(u) : "f"(x));
    return __uint_as_float(u);
}
__device__ __forceinline__ u32 smem_u32(const void* p) {
    u32 a;
    asm("{ .reg .u64 t; cvta.to.shared.u64 t, %1; cvt.u32.u64 %0, t; }" : "=r"(a) : "l"(p));
    return a;
}
#define CP_ASYNC16(saddr, gptr) \
    asm volatile("cp.async.ca.shared.global [%0], [%1], 16;" :: "r"(saddr), "l"(gptr))
#define CP_COMMIT() asm volatile("cp.async.commit_group;" ::: "memory")
#define CP_WAIT(n)  asm volatile("cp.async.wait_group %0;" :: "n"(n) : "memory")

__device__ __forceinline__ void mma_tf32(float* d, const u32* a, const u32* b) {
    asm volatile(
        "mma.sync.aligned.m16n8k8.row.col.f32.tf32.tf32.f32 "
        "{%0,%1,%2,%3}, {%4,%5,%6,%7}, {%8,%9}, {%0,%1,%2,%3};"
        : "+f"(d[0]), "+f"(d[1]), "+f"(d[2]), "+f"(d[3])
        : "r"(a[0]), "r"(a[1]), "r"(a[2]), "r"(a[3]), "r"(b[0]), "r"(b[1]));
}
__device__ __forceinline__ void ldsm_x4(u32* r, u32 saddr) {
    asm volatile("ldmatrix.sync.aligned.m8n8.x4.shared.b16 {%0,%1,%2,%3}, [%4];"
                 : "=r"(r[0]), "=r"(r[1]), "=r"(r[2]), "=r"(r[3]) : "r"(saddr));
}

// ---------------------------------------------------------------------------
__global__ void zero_mem_kernel() {
    size_t i = (size_t)blockIdx.x * blockDim.x + threadIdx.x;  // grid exact: 5*BCD/4
    ((float4*)&g_mem[0][0])[i] = make_float4(0.f, 0.f, 0.f, 0.f);
}

__global__ void vout_copy_kernel(const float* __restrict__ v, float* __restrict__ o) {
    const size_t n4 = (size_t)T_ * BCD / 4;
    size_t i = (size_t)blockIdx.x * blockDim.x + threadIdx.x;
    if (i < n4) {
        float4 val = ((const float4*)v)[i];
        float4* o4 = (float4*)o;
        o4[i]          = val;
        o4[i + n4]     = val;
        o4[i + 2 * n4] = val;
        o4[i + 3 * n4] = val;
    }
}

#define N4_IN  (T_ * BCD / 4)
#define N4_W   (D_ * D_ / 4)
__global__ void cvt_all_kernel(const float4* __restrict__ q, const float4* __restrict__ k,
                               const float4* __restrict__ v, const float4* __restrict__ qw,
                               const float4* __restrict__ kw, const float4* __restrict__ vw,
                               const float4* __restrict__ pw) {
    size_t i = (size_t)blockIdx.x * blockDim.x + threadIdx.x;
    const float4* src;
    float4* dst;
    if (i < 3 * (size_t)N4_IN) {
        int which = (int)(i / N4_IN);
        size_t off = i - (size_t)which * N4_IN;
        src = (which == 0 ? q : (which == 1 ? k : v)) + off;
        dst = (float4*)(which == 0 ? g_cq : (which == 1 ? g_ck : g_cv)) + off;
    } else {
        size_t j = i - 3 * (size_t)N4_IN;
        if (j >= 4 * (size_t)N4_W) return;
        int which = (int)(j / N4_W);
        size_t off = j - (size_t)which * N4_W;
        src = (which == 0 ? qw : (which == 1 ? kw : (which == 2 ? vw : pw))) + off;
        dst = (float4*)&g_wc[which][0] + off;
    }
    float4 x = *src;
    *dst = make_float4(tf32r(x.x), tf32r(x.y), tf32r(x.z), tf32r(x.w));
}

// ---------------------------------------------------------------------------
// Dense TF32 GEMM: CTA tile 128(m)x64(n), BK=32, 2-stage cp.async, 3 CTAs/SM.
// 8 warps 4(m)x2(n); warp tile 32x32 = 2x4 m16n8k8 atoms -> 32 acc regs/thread.
// Stage: A[128][36] (18432B) + B[64][36] (9216B) = 27648B; 2 stages = 55296B.
#define STAGE_BYTES 27648
#define DSM_BYTES   (2 * STAGE_BYTES)

__global__ __launch_bounds__(256, 3) void dense_mma_gemm(
    const float* __restrict__ Xq, const float* __restrict__ Xk, const float* __restrict__ Xv,
    const float* __restrict__ Wq, const float* __restrict__ Wk, const float* __restrict__ Wv,
    const float* __restrict__ bq, const float* __restrict__ bk, const float* __restrict__ bv,
    int mode)
{
    extern __shared__ char dsm[];
    const u32 sb = smem_u32(dsm);

    const int z = blockIdx.z;
    const float* X;
    const float* W;
    const float* bias;
    float* mem = nullptr;
    float* spk = nullptr;
    float* out = nullptr;
    u32*   bitout = nullptr;
    if (mode) {
        X    = (z == 0) ? Xq : ((z == 1) ? Xk : Xv);
        W    = (z == 0) ? Wq : ((z == 1) ? Wk : Wv);
        bias = (z == 0) ? bq : ((z == 1) ? bk : bv);
        mem  = g_mem[z];
        if (z == 2) spk = g_spk2;
        else bitout = (z == 0) ? (u32*)g_qb : (u32*)g_kb;
    } else {
        X = g_spk3; W = Wq; bias = bq; out = g_x2;
    }

    const int tid  = threadIdx.x;
    const int wid  = tid >> 5, lane = tid & 31;
    const int g    = lane >> 2, c = lane & 3;
    const int wm   = wid & 3;       // m quarter (rows wm*32)
    const int wn   = wid >> 2;      // n half (cols wn*32)
    const int m0   = blockIdx.y * 128;
    const int n0   = blockIdx.x * 64;

    float acc[2][4][4];
#pragma unroll
    for (int im = 0; im < 2; im++)
#pragma unroll
        for (int in = 0; in < 4; in++)
#pragma unroll
            for (int r = 0; r < 4; r++) acc[im][in][r] = 0.0f;

    const int row = tid >> 3, seg = tid & 7;

    auto issue_stage = [&](int buf, int chunk) {
        const int k0 = chunk * 32;
        const u32 sA = sb + buf * STAGE_BYTES;
        const u32 sB = sA + 18432;
#pragma unroll
        for (int pass = 0; pass < 4; pass++) {
            int rr = row + pass * 32;
            u32 off = (u32)((rr * 36 + seg * 4) * 4);
            CP_ASYNC16(sA + off, &X[(size_t)(m0 + rr) * 768 + k0 + seg * 4]);
        }
#pragma unroll
        for (int pass = 0; pass < 2; pass++) {
            int rr = row + pass * 32;
            u32 off = (u32)((rr * 36 + seg * 4) * 4);
            CP_ASYNC16(sB + off, &W[(size_t)(n0 + rr) * 768 + k0 + seg * 4]);
        }
    };

    // ldmatrix per-thread base offsets (bytes within a stage)
    const int li = lane & 7, bi = lane >> 3;
    const u32 aOff = (u32)(((wm * 32 + li + ((bi & 1) << 3)) * 36 + ((bi >> 1) << 2)) * 4);
    const u32 bOff = (u32)(18432 + ((wn * 32 + ((bi >> 1) << 3) + li) * 36 + ((bi & 1) << 2)) * 4);

    issue_stage(0, 0); CP_COMMIT();
    issue_stage(1, 1); CP_COMMIT();

    for (int chunk = 0; chunk < 24; chunk++) {
        if (chunk < 23) { CP_WAIT(1); } else { CP_WAIT(0); }
        __syncthreads();

        const u32 stBase = sb + (chunk & 1) * STAGE_BYTES;
#pragma unroll
        for (int ka = 0; ka < 4; ka++) {
            u32 a[2][4], b[4][2];
#pragma unroll
            for (int im = 0; im < 2; im++)
                ldsm_x4(a[im], stBase + aOff + (u32)((im * 16 * 36 + ka * 8) * 4));
#pragma unroll
            for (int ip = 0; ip < 2; ip++) {
                u32 t4[4];
                ldsm_x4(t4, stBase + bOff + (u32)((ip * 16 * 36 + ka * 8) * 4));
                b[2 * ip][0]     = t4[0];
                b[2 * ip][1]     = t4[1];
                b[2 * ip + 1][0] = t4[2];
                b[2 * ip + 1][1] = t4[3];
            }
#pragma unroll
            for (int im = 0; im < 2; im++)
#pragma unroll
                for (int in = 0; in < 4; in++)
                    mma_tf32(acc[im][in], a[im], b[in]);
        }
        // second barrier: everyone done reading this buffer before refill
        __syncthreads();
        if (chunk + 2 < 24) {
            issue_stage(chunk & 1, chunk + 2);
            CP_COMMIT();
        }
    }

    // Epilogue: stage full 128x64 tile (stride 66), then coalesced writeout.
    float* sE = (float*)dsm;                          // 128*66*4 = 33792 B
    double* dredS = (double*)(dsm + 33792);           // 512 doubles
    double* dredQ = (double*)(dsm + 33792 + 4096);    // 512 doubles
    __syncthreads();
#pragma unroll
    for (int im = 0; im < 2; im++)
#pragma unroll
        for (int in = 0; in < 4; in++) {
            int rr   = wm * 32 + im * 16 + g;
            int colb = wn * 32 + in * 8 + 2 * c;
            sE[rr * 66 + colb]           = acc[im][in][0];
            sE[rr * 66 + colb + 1]       = acc[im][in][1];
            sE[(rr + 8) * 66 + colb]     = acc[im][in][2];
            sE[(rr + 8) * 66 + colb + 1] = acc[im][in][3];
        }
    __syncthreads();

    const int head = n0 >> 6;   // N-tile == one head (64 cols, aligned)
#pragma unroll
    for (int nc = 0; nc < 2; nc++) {
        const int nn = n0 + nc * 32 + lane;
        const float bvv = bias[nn];
        double ds = 0.0, dss = 0.0;
        for (int rr = wid * 16; rr < wid * 16 + 16; rr++) {
            float y = sE[rr * 66 + nc * 32 + lane] + bvv;
            int m = m0 + rr;
            size_t idx = (size_t)m * 768 + nn;
            if (mode) {
                float mp    = mem[idx];
                float reset = (mp > 1.0f) ? 1.0f : 0.0f;
                float mn    = 0.6f * mp + y - reset;
                mem[idx] = mn;
                float sp = (mn > 1.0f) ? 1.0f : 0.0f;
                if (z == 2) {
                    spk[idx] = sp;
                } else {
                    u32 bits = __ballot_sync(0xffffffffu, sp > 0.5f);
                    if (lane == 0) bitout[(m * H_ + head) * 2 + nc] = bits;
                }
            } else {
                out[idx] = y;
                ds  += (double)y;
                dss += (double)y * (double)y;
            }
        }
        if (mode == 0) {
            dredS[wid * 64 + nc * 32 + lane] = ds;
            dredQ[wid * 64 + nc * 32 + lane] = dss;
        }
    }

    if (mode == 0) {
        __syncthreads();
        if (tid < 64) {
            double s = 0.0, qq = 0.0;
#pragma unroll
            for (int w = 0; w < 8; w++) {
                s  += dredS[w * 64 + tid];
                qq += dredQ[w * 64 + tid];
            }
            g_bnsum[blockIdx.y * 768 + n0 + tid] = s;
            g_bnsq[blockIdx.y * 768 + n0 + tid]  = qq;
        }
    }
}

// ---------------------------------------------------------------------------
// Fused attention (proven): inline popcount S-frags + HMMA PV + LIF.
__global__ __launch_bounds__(256) void attn_mma_kernel() {
    __shared__ u64   Kb[512];
    __shared__ float Vs[64 * 36];

    const int bh = blockIdx.y;
    const int b  = bh / H_;
    const int h  = bh - b * H_;
    const int i0 = blockIdx.x * 128;
    const int tid = threadIdx.x;
    const int wid = tid >> 5, lane = tid & 31;
    const int g = lane >> 2, cc = lane & 3;

    Kb[tid]       = g_kb[(size_t)(b * C_ + tid) * H_ + h];
    Kb[tid + 256] = g_kb[(size_t)(b * C_ + tid + 256) * H_ + h];

    const int irow0 = i0 + wid * 16 + g;
    const u64 q0 = g_qb[(size_t)(b * C_ + irow0) * H_ + h];
    const u64 q1 = g_qb[(size_t)(b * C_ + irow0 + 8) * H_ + h];

    const float* V = g_spk2 + (size_t)b * C_ * D_ + h * DH;

    float acc[8][4];
#pragma unroll
    for (int in = 0; in < 8; in++)
#pragma unroll
        for (int r = 0; r < 4; r++) acc[in][r] = 0.0f;

    const int vj = tid >> 3, vd = tid & 7;
    float4 va = *(const float4*)&V[(size_t)vj * 768 + vd * 4];
    float4 vb = *(const float4*)&V[(size_t)vj * 768 + 32 + vd * 4];
    __syncthreads();

    const u32* Vsu = (const u32*)Vs;
    for (int c = 0; c < 16; c++) {
        Vs[(4 * vd + 0) * 36 + vj] = va.x;
        Vs[(4 * vd + 1) * 36 + vj] = va.y;
        Vs[(4 * vd + 2) * 36 + vj] = va.z;
        Vs[(4 * vd + 3) * 36 + vj] = va.w;
        Vs[(32 + 4 * vd + 0) * 36 + vj] = vb.x;
        Vs[(32 + 4 * vd + 1) * 36 + vj] = vb.y;
        Vs[(32 + 4 * vd + 2) * 36 + vj] = vb.z;
        Vs[(32 + 4 * vd + 3) * 36 + vj] = vb.w;
        __syncthreads();
        if (c < 15) {
            va = *(const float4*)&V[(size_t)((c + 1) * 32 + vj) * 768 + vd * 4];
            vb = *(const float4*)&V[(size_t)((c + 1) * 32 + vj) * 768 + 32 + vd * 4];
        }

#pragma unroll
        for (int ka = 0; ka < 4; ka++) {
            const int jb = c * 32 + ka * 8;
            const u64 kb0 = Kb[jb + cc];
            const u64 kb4 = Kb[jb + cc + 4];
            u32 a[4];
            a[0] = __float_as_uint(tf32r(0.18f * (float)__popcll(q0 & kb0)));
            a[1] = __float_as_uint(tf32r(0.18f * (float)__popcll(q1 & kb0)));
            a[2] = __float_as_uint(tf32r(0.18f * (float)__popcll(q0 & kb4)));
            a[3] = __float_as_uint(tf32r(0.18f * (float)__popcll(q1 & kb4)));
#pragma unroll
            for (int in = 0; in < 8; in++) {
                u32 bfr[2];
                bfr[0] = Vsu[(in * 8 + g) * 36 + ka * 8 + cc];
                bfr[1] = Vsu[(in * 8 + g) * 36 + ka * 8 + cc + 4];
                mma_tf32(acc[in], a, bfr);
            }
        }
        __syncthreads();
    }

    float* mem = g_mem[3];
    float* spk = g_spk3;
#pragma unroll
    for (int in = 0; in < 8; in++) {
        int col = h * DH + in * 8 + 2 * cc;
        size_t idx0 = (size_t)(b * C_ + irow0) * 768 + col;
        size_t idx1 = (size_t)(b * C_ + irow0 + 8) * 768 + col;
#pragma unroll
        for (int e = 0; e < 2; e++) {
            float mp    = mem[idx0 + e];
            float reset = (mp > 1.0f) ? 1.0f : 0.0f;
            float mn    = 0.6f * mp + acc[in][e] - reset;
            mem[idx0 + e] = mn;
            spk[idx0 + e] = (mn > 1.0f) ? 1.0f : 0.0f;
            float mp1    = mem[idx1 + e];
            float reset1 = (mp1 > 1.0f) ? 1.0f : 0.0f;
            float mn1    = 0.6f * mp1 + acc[in][2 + e] - reset1;
            mem[idx1 + e] = mn1;
            spk[idx1 + e] = (mn1 > 1.0f) ? 1.0f : 0.0f;
        }
    }
}

// ---------------------------------------------------------------------------
__global__ void bn_finalize_kernel() {
    int ch = blockIdx.x * blockDim.x + threadIdx.x;
    if (ch < 768) {
        double s = 0.0, q = 0.0;
#pragma unroll
        for (int p = 0; p < 32; p++) {
            s += g_bnsum[p * 768 + ch];
            q += g_bnsq[p * 768 + ch];
        }
        double mean = s * (1.0 / 4096.0);
        double var  = q * (1.0 / 4096.0) - mean * mean;
        g_mean[ch] = (float)mean;
        g_rstd[ch] = rsqrtf((float)var + 1e-5f);
    }
}

__global__ void bn_apply_lif_kernel(const float* __restrict__ bnw,
                                    const float* __restrict__ bnb,
                                    float* __restrict__ outp) {
    size_t i4 = (size_t)blockIdx.x * blockDim.x + threadIdx.x;
    size_t base = i4 * 4;
    int ch = (int)(base % 768);
    float4 x  = ((const float4*)g_x2)[i4];
    float4 mp = ((const float4*)g_mem[4])[i4];
    float xs[4] = {x.x, x.y, x.z, x.w};
    float ms[4] = {mp.x, mp.y, mp.z, mp.w};
    float4 mo, oo;
    float* mop = (float*)&mo;
    float* oop = (float*)&oo;
#pragma unroll
    for (int j = 0; j < 4; j++) {
        int cj = ch + j;
        float cur = (xs[j] - g_mean[cj]) * g_rstd[cj] * bnw[cj] + bnb[cj];
        float reset = (ms[j] > 1.0f) ? 1.0f : 0.0f;
        float mn    = 0.6f * ms[j] + cur - reset;
        mop[j] = mn;
        oop[j] = (mn > 1.0f) ? 1.0f : 0.0f;
    }
    ((float4*)g_mem[4])[i4] = mo;
    ((float4*)outp)[i4] = oo;
}

// ---------------------------------------------------------------------------
extern "C" void kernel_launch(void* const* d_in, const int* in_sizes, int n_in,
                              void* d_out, int out_size) {
    (void)in_sizes; (void)n_in; (void)out_size;
    const float* q   = (const float*)d_in[0];
    const float* k   = (const float*)d_in[1];
    const float* v   = (const float*)d_in[2];
    const float* qb  = (const float*)d_in[4];
    const float* kb  = (const float*)d_in[6];
    const float* vb  = (const float*)d_in[8];
    const float* pb  = (const float*)d_in[10];
    const float* bnw = (const float*)d_in[11];
    const float* bnb = (const float*)d_in[12];
    float* out = (float*)d_out;

    cudaFuncSetAttribute(dense_mma_gemm, cudaFuncAttributeMaxDynamicSharedMemorySize,
                         DSM_BYTES);

    float* cq; cudaGetSymbolAddress((void**)&cq, g_cq);
    float* ck; cudaGetSymbolAddress((void**)&ck, g_ck);
    float* cv; cudaGetSymbolAddress((void**)&cv, g_cv);
    float* wc; cudaGetSymbolAddress((void**)&wc, g_wc);

    zero_mem_kernel<<<15360, 256>>>();
    vout_copy_kernel<<<12288, 256>>>(v, out + (size_t)T_ * BCD);
    const int totalCvt = 3 * N4_IN + 4 * N4_W;
    cvt_all_kernel<<<(totalCvt + 255) / 256, 256>>>(
        (const float4*)q, (const float4*)k, (const float4*)v,
        (const float4*)d_in[3], (const float4*)d_in[5],
        (const float4*)d_in[7], (const float4*)d_in[9]);

    for (int t = 0; t < T_; t++) {
        const float* qt = cq + (size_t)t * BCD;
        const float* kt = ck + (size_t)t * BCD;
        const float* vt = cv + (size_t)t * BCD;

        dense_mma_gemm<<<dim3(12, 32, 3), 256, DSM_BYTES>>>(
            qt, kt, vt, wc + 0 * D_ * D_, wc + 1 * D_ * D_, wc + 2 * D_ * D_,
            qb, kb, vb, 1);
        attn_mma_kernel<<<dim3(4, 96), 256>>>();
        dense_mma_gemm<<<dim3(12, 32, 1), 256, DSM_BYTES>>>(
            nullptr, nullptr, nullptr, wc + 3 * D_ * D_, nullptr, nullptr,
            pb, nullptr, nullptr, 0);
        bn_finalize_kernel<<<3, 256>>>();
        bn_apply_lif_kernel<<<3072, 256>>>(bnw, bnb, out + (size_t)t * BCD);
    }
}